// round 8
// baseline (speedup 1.0000x reference)
#include <cuda_runtime.h>
#include <cuda_bf16.h>
#include <cstdint>

// Problem constants (fixed by the reference)
#define NN_MAX 50000
#define NF 128      // input feature / hidden width
#define NC 64       // classes

// ---------------- static scratch (no allocations allowed) ----------------
__device__ __align__(128) float g_t1[(size_t)NN_MAX * 256];   // [self(128) | neigh(128)] after GEMM1
__device__ __align__(128) float g_agg1[(size_t)NN_MAX * 128];
__device__ __align__(128) float g_h1[(size_t)NN_MAX * 128];
__device__ __align__(128) float g_t2[(size_t)NN_MAX * 128];   // [q(64) | p(64)] after GEMM2
__device__ __align__(128) float g_agg2[(size_t)NN_MAX * 64];
__device__ __align__(128) float g_deg[NN_MAX];
__device__ __align__(128) float g_invdeg[NN_MAX];
__device__ __align__(128) float g_Wcat1[128 * 256];
__device__ __align__(128) float g_Wcat2[128 * 128];

// ---------------- weight concat ----------------
__global__ void k_concat1(const float* __restrict__ Ws, const float* __restrict__ Wn,
                          float* __restrict__ Wcat) {
    int i = blockIdx.x * blockDim.x + threadIdx.x;   // 128*128 elements
    if (i < 128 * 128) {
        int r = i >> 7, c = i & 127;
        Wcat[r * 256 + c]       = Ws[i];
        Wcat[r * 256 + 128 + c] = Wn[i];
    }
}

__global__ void k_concat2(const float* __restrict__ Ws, const float* __restrict__ Wn,
                          float* __restrict__ Wcat) {
    int i = blockIdx.x * blockDim.x + threadIdx.x;   // 128*64 elements
    if (i < 128 * 64) {
        int r = i / 64, c = i % 64;
        Wcat[r * 128 + c]      = Ws[i];
        Wcat[r * 128 + 64 + c] = Wn[i];
    }
}

// ---------------- SGEMM: C[M,N] = A[M,128] @ B[128,N], N % 128 == 0 ----------------
// BM=BN=128, BK=16, TM=TN=8, 256 threads.
__global__ __launch_bounds__(256) void sgemm_k128(
    const float* __restrict__ A, const float* __restrict__ B,
    float* __restrict__ C, int M, int N)
{
    const int K = 128;
    __shared__ float As[16][132];   // transposed A tile, padded (132*4 bytes, 16B-multiple stride)
    __shared__ float Bs[16][128];

    const int tid = threadIdx.x;
    const int bm = blockIdx.y * 128;
    const int bn = blockIdx.x * 128;
    const int tx = tid & 15;        // N direction
    const int ty = tid >> 4;        // M direction

    float acc[8][8];
#pragma unroll
    for (int m = 0; m < 8; m++)
#pragma unroll
        for (int n = 0; n < 8; n++) acc[m][n] = 0.f;

    for (int kk = 0; kk < K; kk += 16) {
#pragma unroll
        for (int ld = 0; ld < 2; ld++) {
            int f = tid + ld * 256;
            // A tile: 128 rows x 16 cols = 512 float4
            int ar = f >> 2, ac4 = f & 3;
            float4 av = make_float4(0.f, 0.f, 0.f, 0.f);
            if (bm + ar < M)
                av = *reinterpret_cast<const float4*>(A + (size_t)(bm + ar) * K + kk + ac4 * 4);
            As[ac4 * 4 + 0][ar] = av.x;
            As[ac4 * 4 + 1][ar] = av.y;
            As[ac4 * 4 + 2][ar] = av.z;
            As[ac4 * 4 + 3][ar] = av.w;
            // B tile: 16 rows x 128 cols = 512 float4
            int br = f >> 5, bc4 = f & 31;
            float4 bv = *reinterpret_cast<const float4*>(B + (size_t)(kk + br) * N + bn + bc4 * 4);
            *reinterpret_cast<float4*>(&Bs[br][bc4 * 4]) = bv;
        }
        __syncthreads();

#pragma unroll
        for (int k = 0; k < 16; k++) {
            float a_reg[8], b_reg[8];
            *reinterpret_cast<float4*>(&a_reg[0]) = *reinterpret_cast<float4*>(&As[k][ty * 8]);
            *reinterpret_cast<float4*>(&a_reg[4]) = *reinterpret_cast<float4*>(&As[k][ty * 8 + 4]);
            *reinterpret_cast<float4*>(&b_reg[0]) = *reinterpret_cast<float4*>(&Bs[k][tx * 8]);
            *reinterpret_cast<float4*>(&b_reg[4]) = *reinterpret_cast<float4*>(&Bs[k][tx * 8 + 4]);
#pragma unroll
            for (int m = 0; m < 8; m++)
#pragma unroll
                for (int n = 0; n < 8; n++)
                    acc[m][n] = fmaf(a_reg[m], b_reg[n], acc[m][n]);
        }
        __syncthreads();
    }

#pragma unroll
    for (int m = 0; m < 8; m++) {
        int row = bm + ty * 8 + m;
        if (row < M) {
            float4 v0 = make_float4(acc[m][0], acc[m][1], acc[m][2], acc[m][3]);
            float4 v1 = make_float4(acc[m][4], acc[m][5], acc[m][6], acc[m][7]);
            *reinterpret_cast<float4*>(C + (size_t)row * N + bn + tx * 8)     = v0;
            *reinterpret_cast<float4*>(C + (size_t)row * N + bn + tx * 8 + 4) = v1;
        }
    }
}

// ---------------- edge aggregation ----------------
__device__ __forceinline__ void red_add_v4(float* p, float4 v) {
    asm volatile("red.global.add.v4.f32 [%0], {%1,%2,%3,%4};"
                 :: "l"(p), "f"(v.x), "f"(v.y), "f"(v.z), "f"(v.w) : "memory");
}

// Layer 1: one warp per edge, 128 floats/row (t1 col 128..255), also counts degree.
__global__ __launch_bounds__(256) void edge_agg1(
    const float* __restrict__ t1, const int* __restrict__ src, const int* __restrict__ dst,
    float* __restrict__ agg, float* __restrict__ deg, int E)
{
    int gtid  = blockIdx.x * blockDim.x + threadIdx.x;
    int warp  = gtid >> 5;
    int lane  = threadIdx.x & 31;
    int nwarp = (gridDim.x * blockDim.x) >> 5;
    for (int e = warp; e < E; e += nwarp) {
        int s = __ldg(src + e);
        int d = __ldg(dst + e);
        float4 v = __ldg(reinterpret_cast<const float4*>(t1 + (size_t)s * 256 + 128) + lane);
        red_add_v4(agg + (size_t)d * 128 + lane * 4, v);
        if (lane == 0)
            asm volatile("red.global.add.f32 [%0], %1;" :: "l"(deg + d), "f"(1.0f) : "memory");
    }
}

// Layer 2: two edges per warp (16 lanes each), 64 floats/row (t2 col 64..127).
__global__ __launch_bounds__(256) void edge_agg2(
    const float* __restrict__ t2, const int* __restrict__ src, const int* __restrict__ dst,
    float* __restrict__ agg, int E)
{
    int gtid  = blockIdx.x * blockDim.x + threadIdx.x;
    int warp  = gtid >> 5;
    int lane  = threadIdx.x & 31;
    int sub   = lane >> 4;      // which of the 2 edges
    int l     = lane & 15;
    int nwarp = (gridDim.x * blockDim.x) >> 5;
    for (int base = warp * 2; base < E; base += nwarp * 2) {
        int e = base + sub;
        if (e < E) {
            int s = __ldg(src + e);
            int d = __ldg(dst + e);
            float4 v = __ldg(reinterpret_cast<const float4*>(t2 + (size_t)s * 128 + 64) + l);
            red_add_v4(agg + (size_t)d * 64 + l * 4, v);
        }
    }
}

// ---------------- elementwise ----------------
__global__ void k_deg_finalize(const float* __restrict__ deg, float* __restrict__ invdeg, int Nn) {
    int i = blockIdx.x * blockDim.x + threadIdx.x;
    if (i < Nn) invdeg[i] = 1.0f / fmaxf(deg[i], 1.0f);
}

// h1 = relu(t1[:, :128] + agg1 * invdeg + b1)
__global__ void k_combine1(const float* __restrict__ t1, const float* __restrict__ agg1,
                           const float* __restrict__ invdeg, const float* __restrict__ b1,
                           float* __restrict__ h1, int Nn)
{
    int i = blockIdx.x * blockDim.x + threadIdx.x;   // over Nn*32 float4
    int total = Nn * 32;
    if (i >= total) return;
    int node = i >> 5, c4 = i & 31;
    float inv = __ldg(invdeg + node);
    float4 sf = *reinterpret_cast<const float4*>(t1 + (size_t)node * 256 + c4 * 4);
    float4 ag = *reinterpret_cast<const float4*>(agg1 + (size_t)node * 128 + c4 * 4);
    float4 bb = __ldg(reinterpret_cast<const float4*>(b1) + c4);
    float4 o;
    o.x = fmaxf(sf.x + ag.x * inv + bb.x, 0.f);
    o.y = fmaxf(sf.y + ag.y * inv + bb.y, 0.f);
    o.z = fmaxf(sf.z + ag.z * inv + bb.z, 0.f);
    o.w = fmaxf(sf.w + ag.w * inv + bb.w, 0.f);
    *reinterpret_cast<float4*>(h1 + (size_t)node * 128 + c4 * 4) = o;
}

// out = t2[:, :64] + agg2 * invdeg + b2
__global__ void k_combine2(const float* __restrict__ t2, const float* __restrict__ agg2,
                           const float* __restrict__ invdeg, const float* __restrict__ b2,
                           float* __restrict__ out, int Nn)
{
    int i = blockIdx.x * blockDim.x + threadIdx.x;   // over Nn*16 float4
    int total = Nn * 16;
    if (i >= total) return;
    int node = i >> 4, c4 = i & 15;
    float inv = __ldg(invdeg + node);
    float4 sf = *reinterpret_cast<const float4*>(t2 + (size_t)node * 128 + c4 * 4);
    float4 ag = *reinterpret_cast<const float4*>(agg2 + (size_t)node * 64 + c4 * 4);
    float4 bb = __ldg(reinterpret_cast<const float4*>(b2) + c4);
    float4 o;
    o.x = sf.x + ag.x * inv + bb.x;
    o.y = sf.y + ag.y * inv + bb.y;
    o.z = sf.z + ag.z * inv + bb.z;
    o.w = sf.w + ag.w * inv + bb.w;
    *reinterpret_cast<float4*>(out + (size_t)node * 64 + c4 * 4) = o;
}

// ---------------- launch ----------------
extern "C" void kernel_launch(void* const* d_in, const int* in_sizes, int n_in,
                              void* d_out, int out_size)
{
    const float* x   = (const float*)d_in[0];
    const float* Ws1 = (const float*)d_in[1];
    const float* Wn1 = (const float*)d_in[2];
    const float* b1  = (const float*)d_in[3];
    const float* Ws2 = (const float*)d_in[4];
    const float* Wn2 = (const float*)d_in[5];
    const float* b2  = (const float*)d_in[6];
    const int*   src = (const int*)d_in[7];
    const int*   dst = (const int*)d_in[8];
    float* out = (float*)d_out;

    int Nn = in_sizes[0] / NF;
    int E  = in_sizes[7];

    float *t1, *agg1, *h1, *t2, *agg2, *deg, *invdeg, *Wc1, *Wc2;
    cudaGetSymbolAddress((void**)&t1,     g_t1);
    cudaGetSymbolAddress((void**)&agg1,   g_agg1);
    cudaGetSymbolAddress((void**)&h1,     g_h1);
    cudaGetSymbolAddress((void**)&t2,     g_t2);
    cudaGetSymbolAddress((void**)&agg2,   g_agg2);
    cudaGetSymbolAddress((void**)&deg,    g_deg);
    cudaGetSymbolAddress((void**)&invdeg, g_invdeg);
    cudaGetSymbolAddress((void**)&Wc1,    g_Wcat1);
    cudaGetSymbolAddress((void**)&Wc2,    g_Wcat2);

    // zero the accumulators (every call — graph replay must be idempotent)
    cudaMemsetAsync(agg1, 0, (size_t)Nn * 128 * sizeof(float));
    cudaMemsetAsync(agg2, 0, (size_t)Nn * 64 * sizeof(float));
    cudaMemsetAsync(deg,  0, (size_t)Nn * sizeof(float));

    k_concat1<<<(128 * 128 + 255) / 256, 256>>>(Ws1, Wn1, Wc1);
    k_concat2<<<(128 * 64 + 255) / 256, 256>>>(Ws2, Wn2, Wc2);

    // Layer 1
    sgemm_k128<<<dim3(2, (Nn + 127) / 128), 256>>>(x, Wc1, t1, Nn, 256);
    edge_agg1<<<2048, 256>>>(t1, src, dst, agg1, deg, E);
    k_deg_finalize<<<(Nn + 255) / 256, 256>>>(deg, invdeg, Nn);
    k_combine1<<<(Nn * 32 + 255) / 256, 256>>>(t1, agg1, invdeg, b1, h1, Nn);

    // Layer 2
    sgemm_k128<<<dim3(1, (Nn + 127) / 128), 256>>>(h1, Wc2, t2, Nn, 128);
    edge_agg2<<<2048, 256>>>(t2, src, dst, agg2, E);
    k_combine2<<<(Nn * 16 + 255) / 256, 256>>>(t2, agg2, invdeg, b2, out, Nn);
}

// round 9
// speedup vs baseline: 1.2928x; 1.2928x over previous
#include <cuda_runtime.h>
#include <cuda_bf16.h>
#include <cstdint>

// Problem constants (fixed by the reference)
#define NN_MAX 50048
#define E_MAX  840000
#define NF 128      // input feature / hidden width
#define NC 64       // classes

// ---------------- static scratch (no allocations allowed) ----------------
__device__ __align__(128) float g_t1[(size_t)NN_MAX * 256];   // [self(128) | neigh(128)] after GEMM1
__device__ __align__(128) float g_h1[(size_t)NN_MAX * 128];
__device__ __align__(128) float g_t2[(size_t)NN_MAX * 128];   // [self(64) | neigh(64)] after GEMM2
__device__ __align__(128) float g_invdeg[NN_MAX];
__device__ __align__(128) int   g_deg[NN_MAX];
__device__ __align__(128) int   g_incl[NN_MAX];
__device__ __align__(128) int   g_start[NN_MAX];
__device__ __align__(128) int   g_cursor[NN_MAX];
__device__ __align__(128) int   g_csr[E_MAX];
__device__ __align__(128) int   g_bsums[64];
__device__ __align__(128) float g_Wcat1[128 * 256];
__device__ __align__(128) float g_Wcat2[128 * 128];

// ---------------- weight concat ----------------
__global__ void k_concat1(const float* __restrict__ Ws, const float* __restrict__ Wn,
                          float* __restrict__ Wcat) {
    int i = blockIdx.x * blockDim.x + threadIdx.x;   // 128*128 elements
    if (i < 128 * 128) {
        int r = i >> 7, c = i & 127;
        Wcat[r * 256 + c]       = Ws[i];
        Wcat[r * 256 + 128 + c] = Wn[i];
    }
}

__global__ void k_concat2(const float* __restrict__ Ws, const float* __restrict__ Wn,
                          float* __restrict__ Wcat) {
    int i = blockIdx.x * blockDim.x + threadIdx.x;   // 128*64 elements
    if (i < 128 * 64) {
        int r = i / 64, c = i % 64;
        Wcat[r * 128 + c]      = Ws[i];
        Wcat[r * 128 + 64 + c] = Wn[i];
    }
}

// ---------------- CSR build: histogram -> scan -> scatter ----------------
__global__ void k_hist(const int* __restrict__ dst, int* __restrict__ deg, int E) {
    int i = blockIdx.x * blockDim.x + threadIdx.x;
    if (i < E) atomicAdd(deg + __ldg(dst + i), 1);
}

// per-block inclusive scan (block = 1024)
__global__ __launch_bounds__(1024) void k_scan1(const int* __restrict__ deg,
                                                int* __restrict__ incl,
                                                int* __restrict__ bsums, int Nn) {
    __shared__ int sh[1024];
    int i = blockIdx.x * 1024 + threadIdx.x;
    int v = (i < Nn) ? deg[i] : 0;
    sh[threadIdx.x] = v;
    __syncthreads();
#pragma unroll
    for (int o = 1; o < 1024; o <<= 1) {
        int t = (threadIdx.x >= o) ? sh[threadIdx.x - o] : 0;
        __syncthreads();
        sh[threadIdx.x] += t;
        __syncthreads();
    }
    if (i < Nn) incl[i] = sh[threadIdx.x];
    if (threadIdx.x == 1023) bsums[blockIdx.x] = sh[1023];
}

// serial exclusive scan over block sums (nb <= 64)
__global__ void k_scan2(int* __restrict__ bsums, int nb) {
    if (threadIdx.x == 0 && blockIdx.x == 0) {
        int acc = 0;
        for (int i = 0; i < nb; i++) { int t = bsums[i]; bsums[i] = acc; acc += t; }
    }
}

__global__ void k_scan3(const int* __restrict__ deg, const int* __restrict__ incl,
                        const int* __restrict__ bsums, int* __restrict__ start,
                        int* __restrict__ cursor, float* __restrict__ invdeg, int Nn) {
    int i = blockIdx.x * blockDim.x + threadIdx.x;
    if (i < Nn) {
        int d = deg[i];
        int s = incl[i] - d + bsums[i >> 10];
        start[i] = s;
        cursor[i] = s;
        invdeg[i] = 1.0f / fmaxf((float)d, 1.0f);
    }
}

__global__ void k_scatter(const int* __restrict__ src, const int* __restrict__ dst,
                          int* __restrict__ cursor, int* __restrict__ csr, int E) {
    int i = blockIdx.x * blockDim.x + threadIdx.x;
    if (i < E) {
        int p = atomicAdd(cursor + __ldg(dst + i), 1);
        csr[p] = __ldg(src + i);
    }
}

// ---------------- SGEMM: C[M,N] = A[M,128] @ B[128,N], N % 128 == 0 ----------------
// BM=BN=128, BK=16, TM=TN=8, 256 threads.
__global__ __launch_bounds__(256) void sgemm_k128(
    const float* __restrict__ A, const float* __restrict__ B,
    float* __restrict__ C, int M, int N)
{
    const int K = 128;
    __shared__ float As[16][132];   // transposed A tile, padded
    __shared__ float Bs[16][128];

    const int tid = threadIdx.x;
    const int bm = blockIdx.y * 128;
    const int bn = blockIdx.x * 128;
    const int tx = tid & 15;        // N direction
    const int ty = tid >> 4;        // M direction

    float acc[8][8];
#pragma unroll
    for (int m = 0; m < 8; m++)
#pragma unroll
        for (int n = 0; n < 8; n++) acc[m][n] = 0.f;

    for (int kk = 0; kk < K; kk += 16) {
#pragma unroll
        for (int ld = 0; ld < 2; ld++) {
            int f = tid + ld * 256;
            int ar = f >> 2, ac4 = f & 3;
            float4 av = make_float4(0.f, 0.f, 0.f, 0.f);
            if (bm + ar < M)
                av = *reinterpret_cast<const float4*>(A + (size_t)(bm + ar) * K + kk + ac4 * 4);
            As[ac4 * 4 + 0][ar] = av.x;
            As[ac4 * 4 + 1][ar] = av.y;
            As[ac4 * 4 + 2][ar] = av.z;
            As[ac4 * 4 + 3][ar] = av.w;
            int br = f >> 5, bc4 = f & 31;
            float4 bv = *reinterpret_cast<const float4*>(B + (size_t)(kk + br) * N + bn + bc4 * 4);
            *reinterpret_cast<float4*>(&Bs[br][bc4 * 4]) = bv;
        }
        __syncthreads();

#pragma unroll
        for (int k = 0; k < 16; k++) {
            float a_reg[8], b_reg[8];
            *reinterpret_cast<float4*>(&a_reg[0]) = *reinterpret_cast<float4*>(&As[k][ty * 8]);
            *reinterpret_cast<float4*>(&a_reg[4]) = *reinterpret_cast<float4*>(&As[k][ty * 8 + 4]);
            *reinterpret_cast<float4*>(&b_reg[0]) = *reinterpret_cast<float4*>(&Bs[k][tx * 8]);
            *reinterpret_cast<float4*>(&b_reg[4]) = *reinterpret_cast<float4*>(&Bs[k][tx * 8 + 4]);
#pragma unroll
            for (int m = 0; m < 8; m++)
#pragma unroll
                for (int n = 0; n < 8; n++)
                    acc[m][n] = fmaf(a_reg[m], b_reg[n], acc[m][n]);
        }
        __syncthreads();
    }

#pragma unroll
    for (int m = 0; m < 8; m++) {
        int row = bm + ty * 8 + m;
        if (row < M) {
            float4 v0 = make_float4(acc[m][0], acc[m][1], acc[m][2], acc[m][3]);
            float4 v1 = make_float4(acc[m][4], acc[m][5], acc[m][6], acc[m][7]);
            *reinterpret_cast<float4*>(C + (size_t)row * N + bn + tx * 8)     = v0;
            *reinterpret_cast<float4*>(C + (size_t)row * N + bn + tx * 8 + 4) = v1;
        }
    }
}

// ---------------- fused CSR aggregation + combine ----------------
// Layer 1: one warp per node. sum_{s in N(n)} t1[s,128:256]; h1 = relu(t1[n,0:128] + sum*inv + b1)
__global__ __launch_bounds__(256) void k_aggcomb1(
    const float* __restrict__ t1, const int* __restrict__ csr,
    const int* __restrict__ start, const int* __restrict__ deg,
    const float* __restrict__ invdeg, const float* __restrict__ b1,
    float* __restrict__ h1, int Nn)
{
    int warp = (blockIdx.x * blockDim.x + threadIdx.x) >> 5;
    int lane = threadIdx.x & 31;
    if (warp >= Nn) return;
    int s0 = __ldg(start + warp);
    int d  = __ldg(deg + warp);

    float4 acc = make_float4(0.f, 0.f, 0.f, 0.f);
    int i = 0;
    for (; i + 4 <= d; i += 4) {
        int n0 = __ldg(csr + s0 + i);
        int n1 = __ldg(csr + s0 + i + 1);
        int n2 = __ldg(csr + s0 + i + 2);
        int n3 = __ldg(csr + s0 + i + 3);
        float4 v0 = __ldg(reinterpret_cast<const float4*>(t1 + (size_t)n0 * 256 + 128) + lane);
        float4 v1 = __ldg(reinterpret_cast<const float4*>(t1 + (size_t)n1 * 256 + 128) + lane);
        float4 v2 = __ldg(reinterpret_cast<const float4*>(t1 + (size_t)n2 * 256 + 128) + lane);
        float4 v3 = __ldg(reinterpret_cast<const float4*>(t1 + (size_t)n3 * 256 + 128) + lane);
        acc.x += v0.x + v1.x + v2.x + v3.x;
        acc.y += v0.y + v1.y + v2.y + v3.y;
        acc.z += v0.z + v1.z + v2.z + v3.z;
        acc.w += v0.w + v1.w + v2.w + v3.w;
    }
    for (; i < d; i++) {
        int n0 = __ldg(csr + s0 + i);
        float4 v0 = __ldg(reinterpret_cast<const float4*>(t1 + (size_t)n0 * 256 + 128) + lane);
        acc.x += v0.x; acc.y += v0.y; acc.z += v0.z; acc.w += v0.w;
    }

    float inv = __ldg(invdeg + warp);
    float4 sf = *(reinterpret_cast<const float4*>(t1 + (size_t)warp * 256) + lane);
    float4 bb = __ldg(reinterpret_cast<const float4*>(b1) + lane);
    float4 o;
    o.x = fmaxf(fmaf(acc.x, inv, sf.x + bb.x), 0.f);
    o.y = fmaxf(fmaf(acc.y, inv, sf.y + bb.y), 0.f);
    o.z = fmaxf(fmaf(acc.z, inv, sf.z + bb.z), 0.f);
    o.w = fmaxf(fmaf(acc.w, inv, sf.w + bb.w), 0.f);
    *(reinterpret_cast<float4*>(h1 + (size_t)warp * 128) + lane) = o;
}

// Layer 2: half-warp (16 lanes) per node, 64 floats. out = t2[n,0:64] + sum*inv + b2
__global__ __launch_bounds__(256) void k_aggcomb2(
    const float* __restrict__ t2, const int* __restrict__ csr,
    const int* __restrict__ start, const int* __restrict__ deg,
    const float* __restrict__ invdeg, const float* __restrict__ b2,
    float* __restrict__ out, int Nn)
{
    int gtid = blockIdx.x * blockDim.x + threadIdx.x;
    int node = gtid >> 4;
    int l    = threadIdx.x & 15;
    if (node >= Nn) return;
    int s0 = __ldg(start + node);
    int d  = __ldg(deg + node);

    float4 acc = make_float4(0.f, 0.f, 0.f, 0.f);
    int i = 0;
    for (; i + 4 <= d; i += 4) {
        int n0 = __ldg(csr + s0 + i);
        int n1 = __ldg(csr + s0 + i + 1);
        int n2 = __ldg(csr + s0 + i + 2);
        int n3 = __ldg(csr + s0 + i + 3);
        float4 v0 = __ldg(reinterpret_cast<const float4*>(t2 + (size_t)n0 * 128 + 64) + l);
        float4 v1 = __ldg(reinterpret_cast<const float4*>(t2 + (size_t)n1 * 128 + 64) + l);
        float4 v2 = __ldg(reinterpret_cast<const float4*>(t2 + (size_t)n2 * 128 + 64) + l);
        float4 v3 = __ldg(reinterpret_cast<const float4*>(t2 + (size_t)n3 * 128 + 64) + l);
        acc.x += v0.x + v1.x + v2.x + v3.x;
        acc.y += v0.y + v1.y + v2.y + v3.y;
        acc.z += v0.z + v1.z + v2.z + v3.z;
        acc.w += v0.w + v1.w + v2.w + v3.w;
    }
    for (; i < d; i++) {
        int n0 = __ldg(csr + s0 + i);
        float4 v0 = __ldg(reinterpret_cast<const float4*>(t2 + (size_t)n0 * 128 + 64) + l);
        acc.x += v0.x; acc.y += v0.y; acc.z += v0.z; acc.w += v0.w;
    }

    float inv = __ldg(invdeg + node);
    float4 sf = *(reinterpret_cast<const float4*>(t2 + (size_t)node * 128) + l);
    float4 bb = __ldg(reinterpret_cast<const float4*>(b2) + l);
    float4 o;
    o.x = fmaf(acc.x, inv, sf.x + bb.x);
    o.y = fmaf(acc.y, inv, sf.y + bb.y);
    o.z = fmaf(acc.z, inv, sf.z + bb.z);
    o.w = fmaf(acc.w, inv, sf.w + bb.w);
    *(reinterpret_cast<float4*>(out + (size_t)node * 64) + l) = o;
}

// ---------------- launch ----------------
extern "C" void kernel_launch(void* const* d_in, const int* in_sizes, int n_in,
                              void* d_out, int out_size)
{
    const float* x   = (const float*)d_in[0];
    const float* Ws1 = (const float*)d_in[1];
    const float* Wn1 = (const float*)d_in[2];
    const float* b1  = (const float*)d_in[3];
    const float* Ws2 = (const float*)d_in[4];
    const float* Wn2 = (const float*)d_in[5];
    const float* b2  = (const float*)d_in[6];
    const int*   src = (const int*)d_in[7];
    const int*   dst = (const int*)d_in[8];
    float* out = (float*)d_out;

    int Nn = in_sizes[0] / NF;
    int E  = in_sizes[7];

    float *t1, *h1, *t2, *invdeg, *Wc1, *Wc2;
    int *deg, *incl, *start, *cursor, *csr, *bsums;
    cudaGetSymbolAddress((void**)&t1,     g_t1);
    cudaGetSymbolAddress((void**)&h1,     g_h1);
    cudaGetSymbolAddress((void**)&t2,     g_t2);
    cudaGetSymbolAddress((void**)&invdeg, g_invdeg);
    cudaGetSymbolAddress((void**)&deg,    g_deg);
    cudaGetSymbolAddress((void**)&incl,   g_incl);
    cudaGetSymbolAddress((void**)&start,  g_start);
    cudaGetSymbolAddress((void**)&cursor, g_cursor);
    cudaGetSymbolAddress((void**)&csr,    g_csr);
    cudaGetSymbolAddress((void**)&bsums,  g_bsums);
    cudaGetSymbolAddress((void**)&Wc1,    g_Wcat1);
    cudaGetSymbolAddress((void**)&Wc2,    g_Wcat2);

    int nblk = (Nn + 1023) / 1024;

    // CSR build (overlappable with weight concat + GEMM1 in the graph's single stream order)
    cudaMemsetAsync(deg, 0, (size_t)Nn * sizeof(int));
    k_hist<<<(E + 255) / 256, 256>>>(dst, deg, E);
    k_scan1<<<nblk, 1024>>>(deg, incl, bsums, Nn);
    k_scan2<<<1, 32>>>(bsums, nblk);
    k_scan3<<<(Nn + 255) / 256, 256>>>(deg, incl, bsums, start, cursor, invdeg, Nn);
    k_scatter<<<(E + 255) / 256, 256>>>(src, dst, cursor, csr, E);

    k_concat1<<<(128 * 128 + 255) / 256, 256>>>(Ws1, Wn1, Wc1);
    k_concat2<<<(128 * 64 + 255) / 256, 256>>>(Ws2, Wn2, Wc2);

    // Layer 1
    sgemm_k128<<<dim3(2, (Nn + 127) / 128), 256>>>(x, Wc1, t1, Nn, 256);
    k_aggcomb1<<<(Nn * 32 + 255) / 256, 256>>>(t1, csr, start, deg, invdeg, b1, h1, Nn);

    // Layer 2
    sgemm_k128<<<dim3(1, (Nn + 127) / 128), 256>>>(h1, Wc2, t2, Nn, 128);
    k_aggcomb2<<<(Nn * 16 + 255) / 256, 256>>>(t2, csr, start, deg, invdeg, b2, out, Nn);
}

// round 10
// speedup vs baseline: 1.6082x; 1.2440x over previous
#include <cuda_runtime.h>
#include <cuda_bf16.h>
#include <cstdint>

// Problem constants (fixed by the reference)
#define NN_MAX 50048
#define E_MAX  840000
#define NF 128      // input feature / hidden width
#define NC 64       // classes

// ---------------- static scratch (no allocations allowed) ----------------
__device__ __align__(128) float g_t1[(size_t)NN_MAX * 256];   // [self(128) | neigh(128)] after GEMM1
__device__ __align__(128) float g_h1[(size_t)NN_MAX * 128];
__device__ __align__(128) float g_t2[(size_t)NN_MAX * 128];   // [self(64) | neigh(64)] after GEMM2
__device__ __align__(128) float g_invdeg[NN_MAX];
__device__ __align__(128) int   g_deg[NN_MAX];
__device__ __align__(128) int   g_incl[NN_MAX];
__device__ __align__(128) int   g_start[NN_MAX];
__device__ __align__(128) int   g_cursor[NN_MAX];
__device__ __align__(128) int   g_csr[E_MAX];
__device__ __align__(128) int   g_bsums[64];
__device__ __align__(128) float g_Wcat1[128 * 256];
__device__ __align__(128) float g_Wcat2[128 * 128];

// ---------------- weight concat ----------------
__global__ void k_concat1(const float* __restrict__ Ws, const float* __restrict__ Wn,
                          float* __restrict__ Wcat) {
    int i = blockIdx.x * blockDim.x + threadIdx.x;   // 128*128 elements
    if (i < 128 * 128) {
        int r = i >> 7, c = i & 127;
        Wcat[r * 256 + c]       = Ws[i];
        Wcat[r * 256 + 128 + c] = Wn[i];
    }
}

__global__ void k_concat2(const float* __restrict__ Ws, const float* __restrict__ Wn,
                          float* __restrict__ Wcat) {
    int i = blockIdx.x * blockDim.x + threadIdx.x;   // 128*64 elements
    if (i < 128 * 64) {
        int r = i / 64, c = i % 64;
        Wcat[r * 128 + c]      = Ws[i];
        Wcat[r * 128 + 64 + c] = Wn[i];
    }
}

// ---------------- CSR build: histogram -> scan -> scatter ----------------
__global__ void k_hist(const int* __restrict__ dst, int* __restrict__ deg, int E) {
    int i = blockIdx.x * blockDim.x + threadIdx.x;
    if (i < E) atomicAdd(deg + __ldg(dst + i), 1);
}

__global__ __launch_bounds__(1024) void k_scan1(const int* __restrict__ deg,
                                                int* __restrict__ incl,
                                                int* __restrict__ bsums, int Nn) {
    __shared__ int sh[1024];
    int i = blockIdx.x * 1024 + threadIdx.x;
    int v = (i < Nn) ? deg[i] : 0;
    sh[threadIdx.x] = v;
    __syncthreads();
#pragma unroll
    for (int o = 1; o < 1024; o <<= 1) {
        int t = (threadIdx.x >= o) ? sh[threadIdx.x - o] : 0;
        __syncthreads();
        sh[threadIdx.x] += t;
        __syncthreads();
    }
    if (i < Nn) incl[i] = sh[threadIdx.x];
    if (threadIdx.x == 1023) bsums[blockIdx.x] = sh[1023];
}

__global__ void k_scan2(int* __restrict__ bsums, int nb) {
    if (threadIdx.x == 0 && blockIdx.x == 0) {
        int acc = 0;
        for (int i = 0; i < nb; i++) { int t = bsums[i]; bsums[i] = acc; acc += t; }
    }
}

__global__ void k_scan3(const int* __restrict__ deg, const int* __restrict__ incl,
                        const int* __restrict__ bsums, int* __restrict__ start,
                        int* __restrict__ cursor, float* __restrict__ invdeg, int Nn) {
    int i = blockIdx.x * blockDim.x + threadIdx.x;
    if (i < Nn) {
        int d = deg[i];
        int s = incl[i] - d + bsums[i >> 10];
        start[i] = s;
        cursor[i] = s;
        invdeg[i] = 1.0f / fmaxf((float)d, 1.0f);
    }
}

__global__ void k_scatter(const int* __restrict__ src, const int* __restrict__ dst,
                          int* __restrict__ cursor, int* __restrict__ csr, int E) {
    int i = blockIdx.x * blockDim.x + threadIdx.x;
    if (i < E) {
        int p = atomicAdd(cursor + __ldg(dst + i), 1);
        csr[p] = __ldg(src + i);
    }
}

// ---------------- 3xTF32 tensor-core GEMM: C[M,N] = A[M,128] @ B[128,N] ----------------
__device__ __forceinline__ void tf32_split(float v, uint32_t& hi, uint32_t& lo) {
    uint32_t h;
    asm("cvt.rna.tf32.f32 %0, %1;" : "=r"(h) : "f"(v));
    float lf = v - __uint_as_float(h);
    uint32_t l;
    asm("cvt.rna.tf32.f32 %0, %1;" : "=r"(l) : "f"(lf));
    hi = h; lo = l;
}

__device__ __forceinline__ void mma_tf32(float* d, const uint32_t* a, const uint32_t* b) {
    asm volatile(
        "mma.sync.aligned.m16n8k8.row.col.f32.tf32.tf32.f32 "
        "{%0,%1,%2,%3}, {%4,%5,%6,%7}, {%8,%9}, {%0,%1,%2,%3};"
        : "+f"(d[0]), "+f"(d[1]), "+f"(d[2]), "+f"(d[3])
        : "r"(a[0]), "r"(a[1]), "r"(a[2]), "r"(a[3]), "r"(b[0]), "r"(b[1]));
}

// BM=128, BN=128, BK=32, 256 threads = 8 warps in 2(M) x 4(N), warp tile 64x32.
__global__ __launch_bounds__(256, 2) void gemm_tf32_k128(
    const float* __restrict__ A, const float* __restrict__ B,
    float* __restrict__ C, int M, int N)
{
    __shared__ float As[128][36];   // padded: bank-conflict-free fragment loads
    __shared__ float Bs[32][132];

    const int tid  = threadIdx.x;
    const int warp = tid >> 5;
    const int lane = tid & 31;
    const int g    = lane >> 2;     // groupID
    const int tig  = lane & 3;      // thread-in-group
    const int wm   = warp & 1;      // 2 warps in M (x64)
    const int wn   = warp >> 1;     // 4 warps in N (x32)
    const int bm   = blockIdx.y * 128;
    const int bn   = blockIdx.x * 128;

    float acc[4][4][4];             // [mi][ni][frag]
#pragma unroll
    for (int mi = 0; mi < 4; mi++)
#pragma unroll
        for (int ni = 0; ni < 4; ni++)
#pragma unroll
            for (int f = 0; f < 4; f++) acc[mi][ni][f] = 0.f;

    for (int kk = 0; kk < 128; kk += 32) {
        // A tile: 128 x 32 floats = 1024 float4, 4 per thread
#pragma unroll
        for (int i = 0; i < 4; i++) {
            int idx = tid + i * 256;
            int r = idx >> 3, c4 = (idx & 7) * 4;
            float4 v = make_float4(0.f, 0.f, 0.f, 0.f);
            if (bm + r < M)
                v = *reinterpret_cast<const float4*>(A + (size_t)(bm + r) * 128 + kk + c4);
            *reinterpret_cast<float4*>(&As[r][c4]) = v;
        }
        // B tile: 32 x 128 floats = 1024 float4
#pragma unroll
        for (int i = 0; i < 4; i++) {
            int idx = tid + i * 256;
            int r = idx >> 5, c4 = (idx & 31) * 4;
            float4 v = *reinterpret_cast<const float4*>(B + (size_t)(kk + r) * N + bn + c4);
            *reinterpret_cast<float4*>(&Bs[r][c4]) = v;
        }
        __syncthreads();

#pragma unroll
        for (int k8 = 0; k8 < 4; k8++) {
            const int k0 = k8 * 8;
            // A fragments: 4 m16 tiles x 4 vals, split hi/lo
            uint32_t ahi[4][4], alo[4][4];
#pragma unroll
            for (int mi = 0; mi < 4; mi++) {
                int r0 = wm * 64 + mi * 16 + g;
                tf32_split(As[r0    ][k0 + tig    ], ahi[mi][0], alo[mi][0]);
                tf32_split(As[r0 + 8][k0 + tig    ], ahi[mi][1], alo[mi][1]);
                tf32_split(As[r0    ][k0 + tig + 4], ahi[mi][2], alo[mi][2]);
                tf32_split(As[r0 + 8][k0 + tig + 4], ahi[mi][3], alo[mi][3]);
            }
            // B fragments: 4 n8 tiles x 2 vals, split hi/lo
            uint32_t bhi[4][2], blo[4][2];
#pragma unroll
            for (int ni = 0; ni < 4; ni++) {
                int c0 = wn * 32 + ni * 8 + g;
                tf32_split(Bs[k0 + tig    ][c0], bhi[ni][0], blo[ni][0]);
                tf32_split(Bs[k0 + tig + 4][c0], bhi[ni][1], blo[ni][1]);
            }
#pragma unroll
            for (int mi = 0; mi < 4; mi++)
#pragma unroll
                for (int ni = 0; ni < 4; ni++) {
                    mma_tf32(acc[mi][ni], ahi[mi], bhi[ni]);
                    mma_tf32(acc[mi][ni], alo[mi], bhi[ni]);
                    mma_tf32(acc[mi][ni], ahi[mi], blo[ni]);
                }
        }
        __syncthreads();
    }

    // epilogue
#pragma unroll
    for (int mi = 0; mi < 4; mi++) {
#pragma unroll
        for (int ni = 0; ni < 4; ni++) {
            int row0 = bm + wm * 64 + mi * 16 + g;
            int col  = bn + wn * 32 + ni * 8 + tig * 2;
            if (row0 < M)
                *reinterpret_cast<float2*>(C + (size_t)row0 * N + col) =
                    make_float2(acc[mi][ni][0], acc[mi][ni][1]);
            if (row0 + 8 < M)
                *reinterpret_cast<float2*>(C + (size_t)(row0 + 8) * N + col) =
                    make_float2(acc[mi][ni][2], acc[mi][ni][3]);
        }
    }
}

// ---------------- fused CSR aggregation + combine ----------------
__global__ __launch_bounds__(256) void k_aggcomb1(
    const float* __restrict__ t1, const int* __restrict__ csr,
    const int* __restrict__ start, const int* __restrict__ deg,
    const float* __restrict__ invdeg, const float* __restrict__ b1,
    float* __restrict__ h1, int Nn)
{
    int warp = (blockIdx.x * blockDim.x + threadIdx.x) >> 5;
    int lane = threadIdx.x & 31;
    if (warp >= Nn) return;
    int s0 = __ldg(start + warp);
    int d  = __ldg(deg + warp);

    float4 acc = make_float4(0.f, 0.f, 0.f, 0.f);
    int i = 0;
    for (; i + 4 <= d; i += 4) {
        int n0 = __ldg(csr + s0 + i);
        int n1 = __ldg(csr + s0 + i + 1);
        int n2 = __ldg(csr + s0 + i + 2);
        int n3 = __ldg(csr + s0 + i + 3);
        float4 v0 = __ldg(reinterpret_cast<const float4*>(t1 + (size_t)n0 * 256 + 128) + lane);
        float4 v1 = __ldg(reinterpret_cast<const float4*>(t1 + (size_t)n1 * 256 + 128) + lane);
        float4 v2 = __ldg(reinterpret_cast<const float4*>(t1 + (size_t)n2 * 256 + 128) + lane);
        float4 v3 = __ldg(reinterpret_cast<const float4*>(t1 + (size_t)n3 * 256 + 128) + lane);
        acc.x += v0.x + v1.x + v2.x + v3.x;
        acc.y += v0.y + v1.y + v2.y + v3.y;
        acc.z += v0.z + v1.z + v2.z + v3.z;
        acc.w += v0.w + v1.w + v2.w + v3.w;
    }
    for (; i < d; i++) {
        int n0 = __ldg(csr + s0 + i);
        float4 v0 = __ldg(reinterpret_cast<const float4*>(t1 + (size_t)n0 * 256 + 128) + lane);
        acc.x += v0.x; acc.y += v0.y; acc.z += v0.z; acc.w += v0.w;
    }

    float inv = __ldg(invdeg + warp);
    float4 sf = *(reinterpret_cast<const float4*>(t1 + (size_t)warp * 256) + lane);
    float4 bb = __ldg(reinterpret_cast<const float4*>(b1) + lane);
    float4 o;
    o.x = fmaxf(fmaf(acc.x, inv, sf.x + bb.x), 0.f);
    o.y = fmaxf(fmaf(acc.y, inv, sf.y + bb.y), 0.f);
    o.z = fmaxf(fmaf(acc.z, inv, sf.z + bb.z), 0.f);
    o.w = fmaxf(fmaf(acc.w, inv, sf.w + bb.w), 0.f);
    *(reinterpret_cast<float4*>(h1 + (size_t)warp * 128) + lane) = o;
}

__global__ __launch_bounds__(256) void k_aggcomb2(
    const float* __restrict__ t2, const int* __restrict__ csr,
    const int* __restrict__ start, const int* __restrict__ deg,
    const float* __restrict__ invdeg, const float* __restrict__ b2,
    float* __restrict__ out, int Nn)
{
    int gtid = blockIdx.x * blockDim.x + threadIdx.x;
    int node = gtid >> 4;
    int l    = threadIdx.x & 15;
    if (node >= Nn) return;
    int s0 = __ldg(start + node);
    int d  = __ldg(deg + node);

    float4 acc = make_float4(0.f, 0.f, 0.f, 0.f);
    int i = 0;
    for (; i + 4 <= d; i += 4) {
        int n0 = __ldg(csr + s0 + i);
        int n1 = __ldg(csr + s0 + i + 1);
        int n2 = __ldg(csr + s0 + i + 2);
        int n3 = __ldg(csr + s0 + i + 3);
        float4 v0 = __ldg(reinterpret_cast<const float4*>(t2 + (size_t)n0 * 128 + 64) + l);
        float4 v1 = __ldg(reinterpret_cast<const float4*>(t2 + (size_t)n1 * 128 + 64) + l);
        float4 v2 = __ldg(reinterpret_cast<const float4*>(t2 + (size_t)n2 * 128 + 64) + l);
        float4 v3 = __ldg(reinterpret_cast<const float4*>(t2 + (size_t)n3 * 128 + 64) + l);
        acc.x += v0.x + v1.x + v2.x + v3.x;
        acc.y += v0.y + v1.y + v2.y + v3.y;
        acc.z += v0.z + v1.z + v2.z + v3.z;
        acc.w += v0.w + v1.w + v2.w + v3.w;
    }
    for (; i < d; i++) {
        int n0 = __ldg(csr + s0 + i);
        float4 v0 = __ldg(reinterpret_cast<const float4*>(t2 + (size_t)n0 * 128 + 64) + l);
        acc.x += v0.x; acc.y += v0.y; acc.z += v0.z; acc.w += v0.w;
    }

    float inv = __ldg(invdeg + node);
    float4 sf = *(reinterpret_cast<const float4*>(t2 + (size_t)node * 128) + l);
    float4 bb = __ldg(reinterpret_cast<const float4*>(b2) + l);
    float4 o;
    o.x = fmaf(acc.x, inv, sf.x + bb.x);
    o.y = fmaf(acc.y, inv, sf.y + bb.y);
    o.z = fmaf(acc.z, inv, sf.z + bb.z);
    o.w = fmaf(acc.w, inv, sf.w + bb.w);
    *(reinterpret_cast<float4*>(out + (size_t)node * 64) + l) = o;
}

// ---------------- launch ----------------
extern "C" void kernel_launch(void* const* d_in, const int* in_sizes, int n_in,
                              void* d_out, int out_size)
{
    const float* x   = (const float*)d_in[0];
    const float* Ws1 = (const float*)d_in[1];
    const float* Wn1 = (const float*)d_in[2];
    const float* b1  = (const float*)d_in[3];
    const float* Ws2 = (const float*)d_in[4];
    const float* Wn2 = (const float*)d_in[5];
    const float* b2  = (const float*)d_in[6];
    const int*   src = (const int*)d_in[7];
    const int*   dst = (const int*)d_in[8];
    float* out = (float*)d_out;

    int Nn = in_sizes[0] / NF;
    int E  = in_sizes[7];

    float *t1, *h1, *t2, *invdeg, *Wc1, *Wc2;
    int *deg, *incl, *start, *cursor, *csr, *bsums;
    cudaGetSymbolAddress((void**)&t1,     g_t1);
    cudaGetSymbolAddress((void**)&h1,     g_h1);
    cudaGetSymbolAddress((void**)&t2,     g_t2);
    cudaGetSymbolAddress((void**)&invdeg, g_invdeg);
    cudaGetSymbolAddress((void**)&deg,    g_deg);
    cudaGetSymbolAddress((void**)&incl,   g_incl);
    cudaGetSymbolAddress((void**)&start,  g_start);
    cudaGetSymbolAddress((void**)&cursor, g_cursor);
    cudaGetSymbolAddress((void**)&csr,    g_csr);
    cudaGetSymbolAddress((void**)&bsums,  g_bsums);
    cudaGetSymbolAddress((void**)&Wc1,    g_Wcat1);
    cudaGetSymbolAddress((void**)&Wc2,    g_Wcat2);

    int nblk = (Nn + 1023) / 1024;

    // CSR build
    cudaMemsetAsync(deg, 0, (size_t)Nn * sizeof(int));
    k_hist<<<(E + 255) / 256, 256>>>(dst, deg, E);
    k_scan1<<<nblk, 1024>>>(deg, incl, bsums, Nn);
    k_scan2<<<1, 32>>>(bsums, nblk);
    k_scan3<<<(Nn + 255) / 256, 256>>>(deg, incl, bsums, start, cursor, invdeg, Nn);
    k_scatter<<<(E + 255) / 256, 256>>>(src, dst, cursor, csr, E);

    k_concat1<<<(128 * 128 + 255) / 256, 256>>>(Ws1, Wn1, Wc1);
    k_concat2<<<(128 * 64 + 255) / 256, 256>>>(Ws2, Wn2, Wc2);

    // Layer 1
    gemm_tf32_k128<<<dim3(2, (Nn + 127) / 128), 256>>>(x, Wc1, t1, Nn, 256);
    k_aggcomb1<<<(Nn * 32 + 255) / 256, 256>>>(t1, csr, start, deg, invdeg, b1, h1, Nn);

    // Layer 2
    gemm_tf32_k128<<<dim3(1, (Nn + 127) / 128), 256>>>(h1, Wc2, t2, Nn, 128);
    k_aggcomb2<<<(Nn * 16 + 255) / 256, 256>>>(t2, csr, start, deg, invdeg, b2, out, Nn);
}

// round 12
// speedup vs baseline: 2.1230x; 1.3201x over previous
#include <cuda_runtime.h>
#include <cuda_bf16.h>
#include <cstdint>

// Problem constants (fixed by the reference)
#define NN_PAD 50176          // 392 * 128, padded node count
#define E_MAX  840000
#define NF 128

// ---------------- static scratch (no allocations allowed) ----------------
__device__ __align__(128) float g_t1[(size_t)NN_PAD * 256];   // [self(128)|neigh(128)] after GEMM1
__device__ __align__(128) float g_t2[(size_t)NN_PAD * 128];   // [self(64)|neigh(64)] after GEMM2
__device__ __align__(128) __nv_bfloat16 g_h1hi[(size_t)NN_PAD * 128];  // h1 bf16 split (padding stays 0)
__device__ __align__(128) __nv_bfloat16 g_h1lo[(size_t)NN_PAD * 128];
__device__ __align__(128) float g_invdeg[NN_PAD];
__device__ __align__(128) int   g_deg[NN_PAD];
__device__ __align__(128) int   g_incl[NN_PAD];
__device__ __align__(128) int   g_start[NN_PAD];
__device__ __align__(128) int   g_cursor[NN_PAD];
__device__ __align__(128) int   g_csr[E_MAX];
__device__ __align__(128) int   g_bsums[64];
__device__ __align__(128) __nv_bfloat16 g_Bt1hi[256 * 128];   // W1^T (n,k) bf16 hi/lo
__device__ __align__(128) __nv_bfloat16 g_Bt1lo[256 * 128];
__device__ __align__(128) __nv_bfloat16 g_Bt2hi[128 * 128];
__device__ __align__(128) __nv_bfloat16 g_Bt2lo[128 * 128];

__device__ __forceinline__ uint32_t pack_bf2(__nv_bfloat16 a, __nv_bfloat16 b) {
    __nv_bfloat162 t = __halves2bfloat162(a, b);
    return *reinterpret_cast<uint32_t*>(&t);
}

// ---------------- weight prep: W^T + bf16 hi/lo split ----------------
// Bt[n][k] = W[k][n] where W = [Wself | Wneigh] columns; nself = Wself column count.
__global__ void k_prepW(const float* __restrict__ Ws, const float* __restrict__ Wn,
                        int nself, int N,
                        __nv_bfloat16* __restrict__ Bhi, __nv_bfloat16* __restrict__ Blo) {
    int idx = blockIdx.x * blockDim.x + threadIdx.x;
    if (idx >= N * 128) return;
    int n = idx >> 7, k = idx & 127;
    float v = (n < nself) ? Ws[k * nself + n] : Wn[k * nself + (n - nself)];
    __nv_bfloat16 h = __float2bfloat16(v);
    Bhi[idx] = h;
    Blo[idx] = __float2bfloat16(v - __bfloat162float(h));
}

// ---------------- CSR build: histogram -> scan -> scatter ----------------
__global__ void k_hist(const int* __restrict__ dst, int* __restrict__ deg, int E) {
    int i = blockIdx.x * blockDim.x + threadIdx.x;
    if (i < E) atomicAdd(deg + __ldg(dst + i), 1);
}

__global__ __launch_bounds__(1024) void k_scan1(const int* __restrict__ deg,
                                                int* __restrict__ incl,
                                                int* __restrict__ bsums, int Nn) {
    __shared__ int sh[1024];
    int i = blockIdx.x * 1024 + threadIdx.x;
    int v = (i < Nn) ? deg[i] : 0;
    sh[threadIdx.x] = v;
    __syncthreads();
#pragma unroll
    for (int o = 1; o < 1024; o <<= 1) {
        int t = (threadIdx.x >= o) ? sh[threadIdx.x - o] : 0;
        __syncthreads();
        sh[threadIdx.x] += t;
        __syncthreads();
    }
    if (i < Nn) incl[i] = sh[threadIdx.x];
    if (threadIdx.x == 1023) bsums[blockIdx.x] = sh[1023];
}

__global__ void k_scan2(int* __restrict__ bsums, int nb) {
    if (threadIdx.x == 0 && blockIdx.x == 0) {
        int acc = 0;
        for (int i = 0; i < nb; i++) { int t = bsums[i]; bsums[i] = acc; acc += t; }
    }
}

__global__ void k_scan3(const int* __restrict__ deg, const int* __restrict__ incl,
                        const int* __restrict__ bsums, int* __restrict__ start,
                        int* __restrict__ cursor, float* __restrict__ invdeg, int Nn) {
    int i = blockIdx.x * blockDim.x + threadIdx.x;
    if (i < Nn) {
        int d = deg[i];
        int s = incl[i] - d + bsums[i >> 10];
        start[i] = s;
        cursor[i] = s;
        invdeg[i] = 1.0f / fmaxf((float)d, 1.0f);
    }
}

__global__ void k_scatter(const int* __restrict__ src, const int* __restrict__ dst,
                          int* __restrict__ cursor, int* __restrict__ csr, int E) {
    int i = blockIdx.x * blockDim.x + threadIdx.x;
    if (i < E) {
        int p = atomicAdd(cursor + __ldg(dst + i), 1);
        csr[p] = __ldg(src + i);
    }
}

// ---------------- bf16x3 mma.sync GEMM: C[M,N] = A[M,128] @ Bt[N,128]^T ----------------
__device__ __forceinline__ void mma_bf16(float* d, const uint32_t* a, const uint32_t* b) {
    asm volatile(
        "mma.sync.aligned.m16n8k16.row.col.f32.bf16.bf16.f32 "
        "{%0,%1,%2,%3}, {%4,%5,%6,%7}, {%8,%9}, {%0,%1,%2,%3};"
        : "+f"(d[0]), "+f"(d[1]), "+f"(d[2]), "+f"(d[3])
        : "r"(a[0]), "r"(a[1]), "r"(a[2]), "r"(a[3]), "r"(b[0]), "r"(b[1]));
}

#define SMEM_STRIDE 72   // bf16 per row (64 data + 8 pad) -> 36 words, conflict-free frag LDS

__device__ __forceinline__ uint32_t lds_pair(const __nv_bfloat16* s, int r, int c) {
    return *reinterpret_cast<const uint32_t*>(s + r * SMEM_STRIDE + c);
}

// BM=128, BN=128, BK=64 (2 chunks over K=128), 256 threads = 8 warps 2(M)x4(N), warp tile 64x32.
// A either fp32 (split to bf16 hi/lo during smem fill) or pre-split bf16 hi/lo (padded, zeros beyond M).
__global__ __launch_bounds__(256, 2) void gemm_bf16x3(
    const float* __restrict__ A32,
    const __nv_bfloat16* __restrict__ Ahi_g, const __nv_bfloat16* __restrict__ Alo_g,
    const __nv_bfloat16* __restrict__ Bhi_g, const __nv_bfloat16* __restrict__ Blo_g,
    float* __restrict__ C, int M, int N)
{
    extern __shared__ __nv_bfloat16 smem[];
    __nv_bfloat16* sAhi = smem;                       // 128 x 72
    __nv_bfloat16* sAlo = sAhi + 128 * SMEM_STRIDE;
    __nv_bfloat16* sBhi = sAlo + 128 * SMEM_STRIDE;
    __nv_bfloat16* sBlo = sBhi + 128 * SMEM_STRIDE;

    const int tid  = threadIdx.x;
    const int warp = tid >> 5;
    const int lane = tid & 31;
    const int g    = lane >> 2;
    const int tig  = lane & 3;
    const int wm   = warp & 1;      // 2 warps in M (x64)
    const int wn   = warp >> 1;     // 4 warps in N (x32)
    const int bm   = blockIdx.y * 128;
    const int bnb  = blockIdx.x * 128;

    float acc[4][4][4];
#pragma unroll
    for (int mi = 0; mi < 4; mi++)
#pragma unroll
        for (int ni = 0; ni < 4; ni++)
#pragma unroll
            for (int f = 0; f < 4; f++) acc[mi][ni][f] = 0.f;

    for (int kk = 0; kk < 128; kk += 64) {
        if (kk) __syncthreads();

        // ---- fill A (128 rows x 64 k), bf16 hi/lo ----
        if (A32 != nullptr) {
#pragma unroll
            for (int i = 0; i < 8; i++) {
                int idx = tid + i * 256;          // 2048 float4
                int r = idx >> 4, c4 = (idx & 15) * 4;
                float4 v = make_float4(0.f, 0.f, 0.f, 0.f);
                if (bm + r < M)
                    v = *reinterpret_cast<const float4*>(A32 + (size_t)(bm + r) * 128 + kk + c4);
                __nv_bfloat16 hx = __float2bfloat16(v.x), hy = __float2bfloat16(v.y);
                __nv_bfloat16 hz = __float2bfloat16(v.z), hw = __float2bfloat16(v.w);
                __nv_bfloat16 lx = __float2bfloat16(v.x - __bfloat162float(hx));
                __nv_bfloat16 ly = __float2bfloat16(v.y - __bfloat162float(hy));
                __nv_bfloat16 lz = __float2bfloat16(v.z - __bfloat162float(hz));
                __nv_bfloat16 lw = __float2bfloat16(v.w - __bfloat162float(hw));
                int o = r * SMEM_STRIDE + c4;
                *reinterpret_cast<uint2*>(sAhi + o) = make_uint2(pack_bf2(hx, hy), pack_bf2(hz, hw));
                *reinterpret_cast<uint2*>(sAlo + o) = make_uint2(pack_bf2(lx, ly), pack_bf2(lz, lw));
            }
        } else {
#pragma unroll
            for (int i = 0; i < 8; i++) {
                int idx = tid + i * 256;
                int r = idx >> 4, c4 = (idx & 15) * 4;
                int o = r * SMEM_STRIDE + c4;
                *reinterpret_cast<uint2*>(sAhi + o) =
                    *reinterpret_cast<const uint2*>(Ahi_g + (size_t)(bm + r) * 128 + kk + c4);
                *reinterpret_cast<uint2*>(sAlo + o) =
                    *reinterpret_cast<const uint2*>(Alo_g + (size_t)(bm + r) * 128 + kk + c4);
            }
        }

        // ---- fill B (128 n-rows x 64 k), bf16 hi/lo ----
#pragma unroll
        for (int i = 0; i < 8; i++) {
            int idx = tid + i * 256;
            int n = idx >> 4, c4 = (idx & 15) * 4;
            int o = n * SMEM_STRIDE + c4;
            *reinterpret_cast<uint2*>(sBhi + o) =
                *reinterpret_cast<const uint2*>(Bhi_g + (size_t)(bnb + n) * 128 + kk + c4);
            *reinterpret_cast<uint2*>(sBlo + o) =
                *reinterpret_cast<const uint2*>(Blo_g + (size_t)(bnb + n) * 128 + kk + c4);
        }
        __syncthreads();

#pragma unroll
        for (int k16 = 0; k16 < 4; k16++) {
            const int c0 = k16 * 16 + tig * 2;
            // hi fragments
            uint32_t ah[4][4];
#pragma unroll
            for (int mi = 0; mi < 4; mi++) {
                int r0 = wm * 64 + mi * 16 + g;
                ah[mi][0] = lds_pair(sAhi, r0,     c0);
                ah[mi][1] = lds_pair(sAhi, r0 + 8, c0);
                ah[mi][2] = lds_pair(sAhi, r0,     c0 + 8);
                ah[mi][3] = lds_pair(sAhi, r0 + 8, c0 + 8);
            }
            uint32_t bh[4][2];
#pragma unroll
            for (int ni = 0; ni < 4; ni++) {
                int n0 = wn * 32 + ni * 8 + g;
                bh[ni][0] = lds_pair(sBhi, n0, c0);
                bh[ni][1] = lds_pair(sBhi, n0, c0 + 8);
            }
#pragma unroll
            for (int mi = 0; mi < 4; mi++)
#pragma unroll
                for (int ni = 0; ni < 4; ni++) mma_bf16(acc[mi][ni], ah[mi], bh[ni]);

            // Alo x Bhi
            uint32_t al[4][4];
#pragma unroll
            for (int mi = 0; mi < 4; mi++) {
                int r0 = wm * 64 + mi * 16 + g;
                al[mi][0] = lds_pair(sAlo, r0,     c0);
                al[mi][1] = lds_pair(sAlo, r0 + 8, c0);
                al[mi][2] = lds_pair(sAlo, r0,     c0 + 8);
                al[mi][3] = lds_pair(sAlo, r0 + 8, c0 + 8);
            }
#pragma unroll
            for (int mi = 0; mi < 4; mi++)
#pragma unroll
                for (int ni = 0; ni < 4; ni++) mma_bf16(acc[mi][ni], al[mi], bh[ni]);

            // Ahi x Blo
            uint32_t bl[4][2];
#pragma unroll
            for (int ni = 0; ni < 4; ni++) {
                int n0 = wn * 32 + ni * 8 + g;
                bl[ni][0] = lds_pair(sBlo, n0, c0);
                bl[ni][1] = lds_pair(sBlo, n0, c0 + 8);
            }
#pragma unroll
            for (int mi = 0; mi < 4; mi++)
#pragma unroll
                for (int ni = 0; ni < 4; ni++) mma_bf16(acc[mi][ni], ah[mi], bl[ni]);
        }
    }

    // epilogue (C rows padded to NN_PAD; write unconditionally)
#pragma unroll
    for (int mi = 0; mi < 4; mi++) {
#pragma unroll
        for (int ni = 0; ni < 4; ni++) {
            int row = bm + wm * 64 + mi * 16 + g;
            int col = bnb + wn * 32 + ni * 8 + tig * 2;
            *reinterpret_cast<float2*>(C + (size_t)row * N + col) =
                make_float2(acc[mi][ni][0], acc[mi][ni][1]);
            *reinterpret_cast<float2*>(C + (size_t)(row + 8) * N + col) =
                make_float2(acc[mi][ni][2], acc[mi][ni][3]);
        }
    }
}

// ---------------- fused CSR aggregation + combine ----------------
// Layer 1: warp per node; writes h1 as bf16 hi/lo split (feeds GEMM2 directly).
__global__ __launch_bounds__(256) void k_aggcomb1(
    const float* __restrict__ t1, const int* __restrict__ csr,
    const int* __restrict__ start, const int* __restrict__ deg,
    const float* __restrict__ invdeg, const float* __restrict__ b1,
    __nv_bfloat16* __restrict__ h1hi, __nv_bfloat16* __restrict__ h1lo, int Nn)
{
    int warp = (blockIdx.x * blockDim.x + threadIdx.x) >> 5;
    int lane = threadIdx.x & 31;
    if (warp >= Nn) return;
    int s0 = __ldg(start + warp);
    int d  = __ldg(deg + warp);

    float4 acc = make_float4(0.f, 0.f, 0.f, 0.f);
    int i = 0;
    for (; i + 4 <= d; i += 4) {
        int n0 = __ldg(csr + s0 + i);
        int n1 = __ldg(csr + s0 + i + 1);
        int n2 = __ldg(csr + s0 + i + 2);
        int n3 = __ldg(csr + s0 + i + 3);
        float4 v0 = __ldg(reinterpret_cast<const float4*>(t1 + (size_t)n0 * 256 + 128) + lane);
        float4 v1 = __ldg(reinterpret_cast<const float4*>(t1 + (size_t)n1 * 256 + 128) + lane);
        float4 v2 = __ldg(reinterpret_cast<const float4*>(t1 + (size_t)n2 * 256 + 128) + lane);
        float4 v3 = __ldg(reinterpret_cast<const float4*>(t1 + (size_t)n3 * 256 + 128) + lane);
        acc.x += v0.x + v1.x + v2.x + v3.x;
        acc.y += v0.y + v1.y + v2.y + v3.y;
        acc.z += v0.z + v1.z + v2.z + v3.z;
        acc.w += v0.w + v1.w + v2.w + v3.w;
    }
    for (; i < d; i++) {
        int n0 = __ldg(csr + s0 + i);
        float4 v0 = __ldg(reinterpret_cast<const float4*>(t1 + (size_t)n0 * 256 + 128) + lane);
        acc.x += v0.x; acc.y += v0.y; acc.z += v0.z; acc.w += v0.w;
    }

    float inv = __ldg(invdeg + warp);
    float4 sf = *(reinterpret_cast<const float4*>(t1 + (size_t)warp * 256) + lane);
    float4 bb = __ldg(reinterpret_cast<const float4*>(b1) + lane);
    float o[4];
    o[0] = fmaxf(fmaf(acc.x, inv, sf.x + bb.x), 0.f);
    o[1] = fmaxf(fmaf(acc.y, inv, sf.y + bb.y), 0.f);
    o[2] = fmaxf(fmaf(acc.z, inv, sf.z + bb.z), 0.f);
    o[3] = fmaxf(fmaf(acc.w, inv, sf.w + bb.w), 0.f);

    uint32_t hi[2], lo[2];
#pragma unroll
    for (int j = 0; j < 2; j++) {
        __nv_bfloat16 ha = __float2bfloat16(o[2 * j]);
        __nv_bfloat16 hb = __float2bfloat16(o[2 * j + 1]);
        __nv_bfloat16 la = __float2bfloat16(o[2 * j] - __bfloat162float(ha));
        __nv_bfloat16 lb = __float2bfloat16(o[2 * j + 1] - __bfloat162float(hb));
        hi[j] = pack_bf2(ha, hb);
        lo[j] = pack_bf2(la, lb);
    }
    *(reinterpret_cast<uint2*>(h1hi + (size_t)warp * 128) + lane) = make_uint2(hi[0], hi[1]);
    *(reinterpret_cast<uint2*>(h1lo + (size_t)warp * 128) + lane) = make_uint2(lo[0], lo[1]);
}

// Layer 2: half-warp per node, 64 floats. out = t2[n,0:64] + sum*inv + b2
__global__ __launch_bounds__(256) void k_aggcomb2(
    const float* __restrict__ t2, const int* __restrict__ csr,
    const int* __restrict__ start, const int* __restrict__ deg,
    const float* __restrict__ invdeg, const float* __restrict__ b2,
    float* __restrict__ out, int Nn)
{
    int gtid = blockIdx.x * blockDim.x + threadIdx.x;
    int node = gtid >> 4;
    int l    = threadIdx.x & 15;
    if (node >= Nn) return;
    int s0 = __ldg(start + node);
    int d  = __ldg(deg + node);

    float4 acc = make_float4(0.f, 0.f, 0.f, 0.f);
    int i = 0;
    for (; i + 4 <= d; i += 4) {
        int n0 = __ldg(csr + s0 + i);
        int n1 = __ldg(csr + s0 + i + 1);
        int n2 = __ldg(csr + s0 + i + 2);
        int n3 = __ldg(csr + s0 + i + 3);
        float4 v0 = __ldg(reinterpret_cast<const float4*>(t2 + (size_t)n0 * 128 + 64) + l);
        float4 v1 = __ldg(reinterpret_cast<const float4*>(t2 + (size_t)n1 * 128 + 64) + l);
        float4 v2 = __ldg(reinterpret_cast<const float4*>(t2 + (size_t)n2 * 128 + 64) + l);
        float4 v3 = __ldg(reinterpret_cast<const float4*>(t2 + (size_t)n3 * 128 + 64) + l);
        acc.x += v0.x + v1.x + v2.x + v3.x;
        acc.y += v0.y + v1.y + v2.y + v3.y;
        acc.z += v0.z + v1.z + v2.z + v3.z;
        acc.w += v0.w + v1.w + v2.w + v3.w;
    }
    for (; i < d; i++) {
        int n0 = __ldg(csr + s0 + i);
        float4 v0 = __ldg(reinterpret_cast<const float4*>(t2 + (size_t)n0 * 128 + 64) + l);
        acc.x += v0.x; acc.y += v0.y; acc.z += v0.z; acc.w += v0.w;
    }

    float inv = __ldg(invdeg + node);
    float4 sf = *(reinterpret_cast<const float4*>(t2 + (size_t)node * 128) + l);
    float4 bb = __ldg(reinterpret_cast<const float4*>(b2) + l);
    float4 o;
    o.x = fmaf(acc.x, inv, sf.x + bb.x);
    o.y = fmaf(acc.y, inv, sf.y + bb.y);
    o.z = fmaf(acc.z, inv, sf.z + bb.z);
    o.w = fmaf(acc.w, inv, sf.w + bb.w);
    *(reinterpret_cast<float4*>(out + (size_t)node * 64) + l) = o;
}

// ---------------- launch ----------------
extern "C" void kernel_launch(void* const* d_in, const int* in_sizes, int n_in,
                              void* d_out, int out_size)
{
    const float* x   = (const float*)d_in[0];
    const float* Ws1 = (const float*)d_in[1];
    const float* Wn1 = (const float*)d_in[2];
    const float* b1  = (const float*)d_in[3];
    const float* Ws2 = (const float*)d_in[4];
    const float* Wn2 = (const float*)d_in[5];
    const float* b2  = (const float*)d_in[6];
    const int*   src = (const int*)d_in[7];
    const int*   dst = (const int*)d_in[8];
    float* out = (float*)d_out;

    int Nn = in_sizes[0] / NF;
    int E  = in_sizes[7];

    float *t1, *t2, *invdeg;
    __nv_bfloat16 *h1hi, *h1lo, *Bt1hi, *Bt1lo, *Bt2hi, *Bt2lo;
    int *deg, *incl, *start, *cursor, *csr, *bsums;
    cudaGetSymbolAddress((void**)&t1,     g_t1);
    cudaGetSymbolAddress((void**)&t2,     g_t2);
    cudaGetSymbolAddress((void**)&h1hi,   g_h1hi);
    cudaGetSymbolAddress((void**)&h1lo,   g_h1lo);
    cudaGetSymbolAddress((void**)&invdeg, g_invdeg);
    cudaGetSymbolAddress((void**)&deg,    g_deg);
    cudaGetSymbolAddress((void**)&incl,   g_incl);
    cudaGetSymbolAddress((void**)&start,  g_start);
    cudaGetSymbolAddress((void**)&cursor, g_cursor);
    cudaGetSymbolAddress((void**)&csr,    g_csr);
    cudaGetSymbolAddress((void**)&bsums,  g_bsums);
    cudaGetSymbolAddress((void**)&Bt1hi,  g_Bt1hi);
    cudaGetSymbolAddress((void**)&Bt1lo,  g_Bt1lo);
    cudaGetSymbolAddress((void**)&Bt2hi,  g_Bt2hi);
    cudaGetSymbolAddress((void**)&Bt2lo,  g_Bt2lo);

    const int SMEM = 4 * 128 * SMEM_STRIDE * (int)sizeof(__nv_bfloat16);   // 73728
    cudaFuncSetAttribute(gemm_bf16x3, cudaFuncAttributeMaxDynamicSharedMemorySize, SMEM);

    int nblk = (Nn + 1023) / 1024;
    int nmt  = (Nn + 127) / 128;

    // CSR build
    cudaMemsetAsync(deg, 0, (size_t)Nn * sizeof(int));
    k_hist<<<(E + 255) / 256, 256>>>(dst, deg, E);
    k_scan1<<<nblk, 1024>>>(deg, incl, bsums, Nn);
    k_scan2<<<1, 32>>>(bsums, nblk);
    k_scan3<<<(Nn + 255) / 256, 256>>>(deg, incl, bsums, start, cursor, invdeg, Nn);
    k_scatter<<<(E + 255) / 256, 256>>>(src, dst, cursor, csr, E);

    // weight prep (transpose + bf16 split)
    k_prepW<<<(256 * 128 + 255) / 256, 256>>>(Ws1, Wn1, 128, 256, Bt1hi, Bt1lo);
    k_prepW<<<(128 * 128 + 255) / 256, 256>>>(Ws2, Wn2, 64, 128, Bt2hi, Bt2lo);

    // Layer 1 (A = x fp32, split in-kernel)
    gemm_bf16x3<<<dim3(2, nmt), 256, SMEM>>>(x, nullptr, nullptr, Bt1hi, Bt1lo, t1, Nn, 256);
    k_aggcomb1<<<(Nn * 32 + 255) / 256, 256>>>(t1, csr, start, deg, invdeg, b1, h1hi, h1lo, Nn);

    // Layer 2 (A pre-split by aggcomb1; padded rows of h1hi/h1lo stay zero)
    gemm_bf16x3<<<dim3(1, nmt), 256, SMEM>>>(nullptr, h1hi, h1lo, Bt2hi, Bt2lo, t2, Nn, 128);
    k_aggcomb2<<<(Nn * 16 + 255) / 256, 256>>>(t2, csr, start, deg, invdeg, b2, out, Nn);
}

// round 13
// speedup vs baseline: 2.1723x; 1.0232x over previous
#include <cuda_runtime.h>
#include <cuda_bf16.h>
#include <cuda_fp16.h>
#include <cstdint>

// Problem constants (fixed by the reference)
#define NN_PAD 50176          // 392 * 128, padded node count
#define E_MAX  840000
#define NF 128

// ---------------- static scratch (no allocations allowed) ----------------
__device__ __align__(128) float  g_t1s[(size_t)NN_PAD * 128];  // GEMM1 self half (fp32)
__device__ __align__(128) __half g_t1n[(size_t)NN_PAD * 128];  // GEMM1 neigh half (fp16 messages)
__device__ __align__(128) float  g_t2s[(size_t)NN_PAD * 64];   // GEMM2 self half (fp32)
__device__ __align__(128) __half g_t2n[(size_t)NN_PAD * 64];   // GEMM2 neigh half (fp16 messages)
__device__ __align__(128) __nv_bfloat16 g_h1hi[(size_t)NN_PAD * 128];  // h1 bf16 split (padding stays 0)
__device__ __align__(128) __nv_bfloat16 g_h1lo[(size_t)NN_PAD * 128];
__device__ __align__(128) float g_invdeg[NN_PAD];
__device__ __align__(128) int   g_deg[NN_PAD];
__device__ __align__(128) int   g_start[NN_PAD];
__device__ __align__(128) int   g_cursor[NN_PAD];
__device__ __align__(128) int   g_csr[E_MAX];
__device__ __align__(128) int   g_flags[64];
__device__ __align__(128) __nv_bfloat16 g_Bt1hi[256 * 128];   // W1^T (n,k) bf16 hi/lo
__device__ __align__(128) __nv_bfloat16 g_Bt1lo[256 * 128];
__device__ __align__(128) __nv_bfloat16 g_Bt2hi[128 * 128];
__device__ __align__(128) __nv_bfloat16 g_Bt2lo[128 * 128];

__device__ __forceinline__ uint32_t pack_bf2(__nv_bfloat16 a, __nv_bfloat16 b) {
    __nv_bfloat162 t = __halves2bfloat162(a, b);
    return *reinterpret_cast<uint32_t*>(&t);
}

// ---------------- weight prep (both layers, one launch): W^T + bf16 hi/lo split ----------------
__global__ void k_prepW_all(const float* __restrict__ Ws1, const float* __restrict__ Wn1,
                            const float* __restrict__ Ws2, const float* __restrict__ Wn2,
                            __nv_bfloat16* __restrict__ B1hi, __nv_bfloat16* __restrict__ B1lo,
                            __nv_bfloat16* __restrict__ B2hi, __nv_bfloat16* __restrict__ B2lo) {
    int idx = blockIdx.x * blockDim.x + threadIdx.x;
    if (idx < 256 * 128) {
        int n = idx >> 7, k = idx & 127;
        float v = (n < 128) ? Ws1[k * 128 + n] : Wn1[k * 128 + (n - 128)];
        __nv_bfloat16 h = __float2bfloat16(v);
        B1hi[idx] = h;
        B1lo[idx] = __float2bfloat16(v - __bfloat162float(h));
    } else if (idx < 256 * 128 + 128 * 128) {
        int i2 = idx - 256 * 128;
        int n = i2 >> 7, k = i2 & 127;
        float v = (n < 64) ? Ws2[k * 64 + n] : Wn2[k * 64 + (n - 64)];
        __nv_bfloat16 h = __float2bfloat16(v);
        B2hi[i2] = h;
        B2lo[i2] = __float2bfloat16(v - __bfloat162float(h));
    }
}

// ---------------- CSR build: histogram -> fused scan -> scatter ----------------
__global__ void k_hist(const int* __restrict__ dst, int* __restrict__ deg,
                       int* __restrict__ flags, int E) {
    int i = blockIdx.x * blockDim.x + threadIdx.x;
    if (i < 64) flags[i] = 0;                     // zero scan flags (read only after this kernel)
    if (i < E) atomicAdd(deg + __ldg(dst + i), 1);
}

// single-launch scan: per-block inclusive scan + inter-block prefix propagation (grid <= 64 < #SM)
__global__ __launch_bounds__(1024) void k_scan_fused(
    const int* __restrict__ deg, int* __restrict__ flags,
    int* __restrict__ start, int* __restrict__ cursor,
    float* __restrict__ invdeg, int Nn)
{
    __shared__ int sh[1024];
    __shared__ int s_prefix;
    int i = blockIdx.x * 1024 + threadIdx.x;
    int v = (i < Nn) ? deg[i] : 0;
    sh[threadIdx.x] = v;
    __syncthreads();
#pragma unroll
    for (int o = 1; o < 1024; o <<= 1) {
        int t = (threadIdx.x >= o) ? sh[threadIdx.x - o] : 0;
        __syncthreads();
        sh[threadIdx.x] += t;
        __syncthreads();
    }
    int incl = sh[threadIdx.x];
    if (threadIdx.x == 1023) {
        int prefix = 0;
        if (blockIdx.x > 0) {
            int t;
            while ((t = atomicAdd(flags + blockIdx.x - 1, 0)) == 0) {}
            prefix = t - 1;                       // stored value = inclusive prefix + 1
        }
        atomicExch(flags + blockIdx.x, prefix + incl + 1);
        s_prefix = prefix;
    }
    __syncthreads();
    if (i < Nn) {
        int s = s_prefix + incl - v;
        start[i]  = s;
        cursor[i] = s;
        invdeg[i] = 1.0f / fmaxf((float)v, 1.0f);
    }
}

__global__ void k_scatter(const int* __restrict__ src, const int* __restrict__ dst,
                          int* __restrict__ cursor, int* __restrict__ csr, int E) {
    int i = blockIdx.x * blockDim.x + threadIdx.x;
    if (i < E) {
        int p = atomicAdd(cursor + __ldg(dst + i), 1);
        csr[p] = __ldg(src + i);
    }
}

// ---------------- bf16x3 mma.sync GEMM: [self fp32 | neigh fp16] = A[M,128] @ Bt[N,128]^T ----------------
__device__ __forceinline__ void mma_bf16(float* d, const uint32_t* a, const uint32_t* b) {
    asm volatile(
        "mma.sync.aligned.m16n8k16.row.col.f32.bf16.bf16.f32 "
        "{%0,%1,%2,%3}, {%4,%5,%6,%7}, {%8,%9}, {%0,%1,%2,%3};"
        : "+f"(d[0]), "+f"(d[1]), "+f"(d[2]), "+f"(d[3])
        : "r"(a[0]), "r"(a[1]), "r"(a[2]), "r"(a[3]), "r"(b[0]), "r"(b[1]));
}

#define SMEM_STRIDE 72   // bf16 per row (64 data + 8 pad)

__device__ __forceinline__ uint32_t lds_pair(const __nv_bfloat16* s, int r, int c) {
    return *reinterpret_cast<const uint32_t*>(s + r * SMEM_STRIDE + c);
}

// BM=128, BN=128, BK=64, 256 threads = 8 warps 2(M)x4(N), warp tile 64x32.
// Cols < ncut -> Cself fp32 (stride ncut); cols >= ncut -> Cn fp16 (stride N-ncut).
__global__ __launch_bounds__(256, 2) void gemm_bf16x3(
    const float* __restrict__ A32,
    const __nv_bfloat16* __restrict__ Ahi_g, const __nv_bfloat16* __restrict__ Alo_g,
    const __nv_bfloat16* __restrict__ Bhi_g, const __nv_bfloat16* __restrict__ Blo_g,
    float* __restrict__ Cself, __half* __restrict__ Cn, int M, int N, int ncut)
{
    extern __shared__ __nv_bfloat16 smem[];
    __nv_bfloat16* sAhi = smem;                       // 128 x 72
    __nv_bfloat16* sAlo = sAhi + 128 * SMEM_STRIDE;
    __nv_bfloat16* sBhi = sAlo + 128 * SMEM_STRIDE;
    __nv_bfloat16* sBlo = sBhi + 128 * SMEM_STRIDE;

    const int tid  = threadIdx.x;
    const int warp = tid >> 5;
    const int lane = tid & 31;
    const int g    = lane >> 2;
    const int tig  = lane & 3;
    const int wm   = warp & 1;
    const int wn   = warp >> 1;
    const int bm   = blockIdx.y * 128;
    const int bnb  = blockIdx.x * 128;

    float acc[4][4][4];
#pragma unroll
    for (int mi = 0; mi < 4; mi++)
#pragma unroll
        for (int ni = 0; ni < 4; ni++)
#pragma unroll
            for (int f = 0; f < 4; f++) acc[mi][ni][f] = 0.f;

    for (int kk = 0; kk < 128; kk += 64) {
        if (kk) __syncthreads();

        if (A32 != nullptr) {
#pragma unroll
            for (int i = 0; i < 8; i++) {
                int idx = tid + i * 256;
                int r = idx >> 4, c4 = (idx & 15) * 4;
                float4 v = make_float4(0.f, 0.f, 0.f, 0.f);
                if (bm + r < M)
                    v = *reinterpret_cast<const float4*>(A32 + (size_t)(bm + r) * 128 + kk + c4);
                __nv_bfloat16 hx = __float2bfloat16(v.x), hy = __float2bfloat16(v.y);
                __nv_bfloat16 hz = __float2bfloat16(v.z), hw = __float2bfloat16(v.w);
                __nv_bfloat16 lx = __float2bfloat16(v.x - __bfloat162float(hx));
                __nv_bfloat16 ly = __float2bfloat16(v.y - __bfloat162float(hy));
                __nv_bfloat16 lz = __float2bfloat16(v.z - __bfloat162float(hz));
                __nv_bfloat16 lw = __float2bfloat16(v.w - __bfloat162float(hw));
                int o = r * SMEM_STRIDE + c4;
                *reinterpret_cast<uint2*>(sAhi + o) = make_uint2(pack_bf2(hx, hy), pack_bf2(hz, hw));
                *reinterpret_cast<uint2*>(sAlo + o) = make_uint2(pack_bf2(lx, ly), pack_bf2(lz, lw));
            }
        } else {
#pragma unroll
            for (int i = 0; i < 8; i++) {
                int idx = tid + i * 256;
                int r = idx >> 4, c4 = (idx & 15) * 4;
                int o = r * SMEM_STRIDE + c4;
                *reinterpret_cast<uint2*>(sAhi + o) =
                    *reinterpret_cast<const uint2*>(Ahi_g + (size_t)(bm + r) * 128 + kk + c4);
                *reinterpret_cast<uint2*>(sAlo + o) =
                    *reinterpret_cast<const uint2*>(Alo_g + (size_t)(bm + r) * 128 + kk + c4);
            }
        }

#pragma unroll
        for (int i = 0; i < 8; i++) {
            int idx = tid + i * 256;
            int n = idx >> 4, c4 = (idx & 15) * 4;
            int o = n * SMEM_STRIDE + c4;
            *reinterpret_cast<uint2*>(sBhi + o) =
                *reinterpret_cast<const uint2*>(Bhi_g + (size_t)(bnb + n) * 128 + kk + c4);
            *reinterpret_cast<uint2*>(sBlo + o) =
                *reinterpret_cast<const uint2*>(Blo_g + (size_t)(bnb + n) * 128 + kk + c4);
        }
        __syncthreads();

#pragma unroll
        for (int k16 = 0; k16 < 4; k16++) {
            const int c0 = k16 * 16 + tig * 2;
            uint32_t ah[4][4];
#pragma unroll
            for (int mi = 0; mi < 4; mi++) {
                int r0 = wm * 64 + mi * 16 + g;
                ah[mi][0] = lds_pair(sAhi, r0,     c0);
                ah[mi][1] = lds_pair(sAhi, r0 + 8, c0);
                ah[mi][2] = lds_pair(sAhi, r0,     c0 + 8);
                ah[mi][3] = lds_pair(sAhi, r0 + 8, c0 + 8);
            }
            uint32_t bh[4][2];
#pragma unroll
            for (int ni = 0; ni < 4; ni++) {
                int n0 = wn * 32 + ni * 8 + g;
                bh[ni][0] = lds_pair(sBhi, n0, c0);
                bh[ni][1] = lds_pair(sBhi, n0, c0 + 8);
            }
#pragma unroll
            for (int mi = 0; mi < 4; mi++)
#pragma unroll
                for (int ni = 0; ni < 4; ni++) mma_bf16(acc[mi][ni], ah[mi], bh[ni]);

            uint32_t al[4][4];
#pragma unroll
            for (int mi = 0; mi < 4; mi++) {
                int r0 = wm * 64 + mi * 16 + g;
                al[mi][0] = lds_pair(sAlo, r0,     c0);
                al[mi][1] = lds_pair(sAlo, r0 + 8, c0);
                al[mi][2] = lds_pair(sAlo, r0,     c0 + 8);
                al[mi][3] = lds_pair(sAlo, r0 + 8, c0 + 8);
            }
#pragma unroll
            for (int mi = 0; mi < 4; mi++)
#pragma unroll
                for (int ni = 0; ni < 4; ni++) mma_bf16(acc[mi][ni], al[mi], bh[ni]);

            uint32_t bl[4][2];
#pragma unroll
            for (int ni = 0; ni < 4; ni++) {
                int n0 = wn * 32 + ni * 8 + g;
                bl[ni][0] = lds_pair(sBlo, n0, c0);
                bl[ni][1] = lds_pair(sBlo, n0, c0 + 8);
            }
#pragma unroll
            for (int mi = 0; mi < 4; mi++)
#pragma unroll
                for (int ni = 0; ni < 4; ni++) mma_bf16(acc[mi][ni], ah[mi], bl[ni]);
        }
    }

    // epilogue: self half -> fp32 Cself[*, ncut]; neigh half -> fp16 Cn[*, N-ncut]
    const int nw = N - ncut;
#pragma unroll
    for (int mi = 0; mi < 4; mi++) {
#pragma unroll
        for (int ni = 0; ni < 4; ni++) {
            int row = bm + wm * 64 + mi * 16 + g;
            int col = bnb + wn * 32 + ni * 8 + tig * 2;
            if (col < ncut) {
                *reinterpret_cast<float2*>(Cself + (size_t)row * ncut + col) =
                    make_float2(acc[mi][ni][0], acc[mi][ni][1]);
                *reinterpret_cast<float2*>(Cself + (size_t)(row + 8) * ncut + col) =
                    make_float2(acc[mi][ni][2], acc[mi][ni][3]);
            } else {
                int c = col - ncut;
                *reinterpret_cast<__half2*>(Cn + (size_t)row * nw + c) =
                    __floats2half2_rn(acc[mi][ni][0], acc[mi][ni][1]);
                *reinterpret_cast<__half2*>(Cn + (size_t)(row + 8) * nw + c) =
                    __floats2half2_rn(acc[mi][ni][2], acc[mi][ni][3]);
            }
        }
    }
}

// ---------------- fused CSR aggregation + combine ----------------
__device__ __forceinline__ void acc_half4(float4& acc, uint2 u) {
    float2 f0 = __half22float2(*reinterpret_cast<__half2*>(&u.x));
    float2 f1 = __half22float2(*reinterpret_cast<__half2*>(&u.y));
    acc.x += f0.x; acc.y += f0.y; acc.z += f1.x; acc.w += f1.y;
}

// Layer 1: warp per node; gathers fp16 messages (256B/row); writes h1 as bf16 hi/lo split.
__global__ __launch_bounds__(256) void k_aggcomb1(
    const float* __restrict__ t1s, const __half* __restrict__ t1n,
    const int* __restrict__ csr, const int* __restrict__ start, const int* __restrict__ deg,
    const float* __restrict__ invdeg, const float* __restrict__ b1,
    __nv_bfloat16* __restrict__ h1hi, __nv_bfloat16* __restrict__ h1lo, int Nn)
{
    int warp = (blockIdx.x * blockDim.x + threadIdx.x) >> 5;
    int lane = threadIdx.x & 31;
    if (warp >= Nn) return;
    int s0 = __ldg(start + warp);
    int d  = __ldg(deg + warp);

    float4 acc = make_float4(0.f, 0.f, 0.f, 0.f);
    int i = 0;
    for (; i + 4 <= d; i += 4) {
        int n0 = __ldg(csr + s0 + i);
        int n1 = __ldg(csr + s0 + i + 1);
        int n2 = __ldg(csr + s0 + i + 2);
        int n3 = __ldg(csr + s0 + i + 3);
        uint2 u0 = __ldg(reinterpret_cast<const uint2*>(t1n + (size_t)n0 * 128) + lane);
        uint2 u1 = __ldg(reinterpret_cast<const uint2*>(t1n + (size_t)n1 * 128) + lane);
        uint2 u2 = __ldg(reinterpret_cast<const uint2*>(t1n + (size_t)n2 * 128) + lane);
        uint2 u3 = __ldg(reinterpret_cast<const uint2*>(t1n + (size_t)n3 * 128) + lane);
        acc_half4(acc, u0); acc_half4(acc, u1); acc_half4(acc, u2); acc_half4(acc, u3);
    }
    for (; i < d; i++) {
        int n0 = __ldg(csr + s0 + i);
        uint2 u0 = __ldg(reinterpret_cast<const uint2*>(t1n + (size_t)n0 * 128) + lane);
        acc_half4(acc, u0);
    }

    float inv = __ldg(invdeg + warp);
    float4 sf = *(reinterpret_cast<const float4*>(t1s + (size_t)warp * 128) + lane);
    float4 bb = __ldg(reinterpret_cast<const float4*>(b1) + lane);
    float o[4];
    o[0] = fmaxf(fmaf(acc.x, inv, sf.x + bb.x), 0.f);
    o[1] = fmaxf(fmaf(acc.y, inv, sf.y + bb.y), 0.f);
    o[2] = fmaxf(fmaf(acc.z, inv, sf.z + bb.z), 0.f);
    o[3] = fmaxf(fmaf(acc.w, inv, sf.w + bb.w), 0.f);

    uint32_t hi[2], lo[2];
#pragma unroll
    for (int j = 0; j < 2; j++) {
        __nv_bfloat16 ha = __float2bfloat16(o[2 * j]);
        __nv_bfloat16 hb = __float2bfloat16(o[2 * j + 1]);
        __nv_bfloat16 la = __float2bfloat16(o[2 * j] - __bfloat162float(ha));
        __nv_bfloat16 lb = __float2bfloat16(o[2 * j + 1] - __bfloat162float(hb));
        hi[j] = pack_bf2(ha, hb);
        lo[j] = pack_bf2(la, lb);
    }
    *(reinterpret_cast<uint2*>(h1hi + (size_t)warp * 128) + lane) = make_uint2(hi[0], hi[1]);
    *(reinterpret_cast<uint2*>(h1lo + (size_t)warp * 128) + lane) = make_uint2(lo[0], lo[1]);
}

// Layer 2: half-warp per node; gathers fp16 messages (128B/row). out = t2s + mean*inv + b2
__global__ __launch_bounds__(256) void k_aggcomb2(
    const float* __restrict__ t2s, const __half* __restrict__ t2n,
    const int* __restrict__ csr, const int* __restrict__ start, const int* __restrict__ deg,
    const float* __restrict__ invdeg, const float* __restrict__ b2,
    float* __restrict__ out, int Nn)
{
    int gtid = blockIdx.x * blockDim.x + threadIdx.x;
    int node = gtid >> 4;
    int l    = threadIdx.x & 15;
    if (node >= Nn) return;
    int s0 = __ldg(start + node);
    int d  = __ldg(deg + node);

    float4 acc = make_float4(0.f, 0.f, 0.f, 0.f);
    int i = 0;
    for (; i + 4 <= d; i += 4) {
        int n0 = __ldg(csr + s0 + i);
        int n1 = __ldg(csr + s0 + i + 1);
        int n2 = __ldg(csr + s0 + i + 2);
        int n3 = __ldg(csr + s0 + i + 3);
        uint2 u0 = __ldg(reinterpret_cast<const uint2*>(t2n + (size_t)n0 * 64) + l);
        uint2 u1 = __ldg(reinterpret_cast<const uint2*>(t2n + (size_t)n1 * 64) + l);
        uint2 u2 = __ldg(reinterpret_cast<const uint2*>(t2n + (size_t)n2 * 64) + l);
        uint2 u3 = __ldg(reinterpret_cast<const uint2*>(t2n + (size_t)n3 * 64) + l);
        acc_half4(acc, u0); acc_half4(acc, u1); acc_half4(acc, u2); acc_half4(acc, u3);
    }
    for (; i < d; i++) {
        int n0 = __ldg(csr + s0 + i);
        uint2 u0 = __ldg(reinterpret_cast<const uint2*>(t2n + (size_t)n0 * 64) + l);
        acc_half4(acc, u0);
    }

    float inv = __ldg(invdeg + node);
    float4 sf = *(reinterpret_cast<const float4*>(t2s + (size_t)node * 64) + l);
    float4 bb = __ldg(reinterpret_cast<const float4*>(b2) + l);
    float4 o;
    o.x = fmaf(acc.x, inv, sf.x + bb.x);
    o.y = fmaf(acc.y, inv, sf.y + bb.y);
    o.z = fmaf(acc.z, inv, sf.z + bb.z);
    o.w = fmaf(acc.w, inv, sf.w + bb.w);
    *(reinterpret_cast<float4*>(out + (size_t)node * 64) + l) = o;
}

// ---------------- launch ----------------
extern "C" void kernel_launch(void* const* d_in, const int* in_sizes, int n_in,
                              void* d_out, int out_size)
{
    const float* x   = (const float*)d_in[0];
    const float* Ws1 = (const float*)d_in[1];
    const float* Wn1 = (const float*)d_in[2];
    const float* b1  = (const float*)d_in[3];
    const float* Ws2 = (const float*)d_in[4];
    const float* Wn2 = (const float*)d_in[5];
    const float* b2  = (const float*)d_in[6];
    const int*   src = (const int*)d_in[7];
    const int*   dst = (const int*)d_in[8];
    float* out = (float*)d_out;

    int Nn = in_sizes[0] / NF;
    int E  = in_sizes[7];

    float *t1s, *t2s, *invdeg;
    __half *t1n, *t2n;
    __nv_bfloat16 *h1hi, *h1lo, *Bt1hi, *Bt1lo, *Bt2hi, *Bt2lo;
    int *deg, *start, *cursor, *csr, *flags;
    cudaGetSymbolAddress((void**)&t1s,    g_t1s);
    cudaGetSymbolAddress((void**)&t1n,    g_t1n);
    cudaGetSymbolAddress((void**)&t2s,    g_t2s);
    cudaGetSymbolAddress((void**)&t2n,    g_t2n);
    cudaGetSymbolAddress((void**)&h1hi,   g_h1hi);
    cudaGetSymbolAddress((void**)&h1lo,   g_h1lo);
    cudaGetSymbolAddress((void**)&invdeg, g_invdeg);
    cudaGetSymbolAddress((void**)&deg,    g_deg);
    cudaGetSymbolAddress((void**)&start,  g_start);
    cudaGetSymbolAddress((void**)&cursor, g_cursor);
    cudaGetSymbolAddress((void**)&csr,    g_csr);
    cudaGetSymbolAddress((void**)&flags,  g_flags);
    cudaGetSymbolAddress((void**)&Bt1hi,  g_Bt1hi);
    cudaGetSymbolAddress((void**)&Bt1lo,  g_Bt1lo);
    cudaGetSymbolAddress((void**)&Bt2hi,  g_Bt2hi);
    cudaGetSymbolAddress((void**)&Bt2lo,  g_Bt2lo);

    const int SMEM = 4 * 128 * SMEM_STRIDE * (int)sizeof(__nv_bfloat16);   // 73728
    cudaFuncSetAttribute(gemm_bf16x3, cudaFuncAttributeMaxDynamicSharedMemorySize, SMEM);

    int nblk = (Nn + 1023) / 1024;
    int nmt  = (Nn + 127) / 128;

    // CSR build (4 nodes)
    cudaMemsetAsync(deg, 0, (size_t)Nn * sizeof(int));
    k_hist<<<(E + 255) / 256, 256>>>(dst, deg, flags, E);
    k_scan_fused<<<nblk, 1024>>>(deg, flags, start, cursor, invdeg, Nn);
    k_scatter<<<(E + 255) / 256, 256>>>(src, dst, cursor, csr, E);

    // weight prep (1 node)
    k_prepW_all<<<(256 * 128 + 128 * 128 + 255) / 256, 256>>>(Ws1, Wn1, Ws2, Wn2,
                                                              Bt1hi, Bt1lo, Bt2hi, Bt2lo);

    // Layer 1
    gemm_bf16x3<<<dim3(2, nmt), 256, SMEM>>>(x, nullptr, nullptr, Bt1hi, Bt1lo,
                                             t1s, t1n, Nn, 256, 128);
    k_aggcomb1<<<(Nn * 32 + 255) / 256, 256>>>(t1s, t1n, csr, start, deg, invdeg, b1,
                                               h1hi, h1lo, Nn);

    // Layer 2
    gemm_bf16x3<<<dim3(1, nmt), 256, SMEM>>>(nullptr, h1hi, h1lo, Bt2hi, Bt2lo,
                                             t2s, t2n, Nn, 128, 64);
    k_aggcomb2<<<(Nn * 16 + 255) / 256, 256>>>(t2s, t2n, csr, start, deg, invdeg, b2, out, Nn);
}

// round 14
// speedup vs baseline: 2.1814x; 1.0042x over previous
#include <cuda_runtime.h>
#include <cuda_bf16.h>
#include <cuda_fp16.h>
#include <cstdint>

// Problem constants (fixed by the reference)
#define NN_PAD 50176          // 392 * 128, padded node count
#define E_MAX  840000
#define NF 128

// ---------------- static scratch (no allocations allowed) ----------------
__device__ __align__(128) float  g_t1s[(size_t)NN_PAD * 128];  // GEMM1 self half (fp32)
__device__ __align__(128) __half g_t1n[(size_t)NN_PAD * 128];  // GEMM1 neigh half (fp16 messages)
__device__ __align__(128) float  g_t2s[(size_t)NN_PAD * 64];   // GEMM2 self half (fp32)
__device__ __align__(128) __half g_t2n[(size_t)NN_PAD * 64];   // GEMM2 neigh half (fp16 messages)
__device__ __align__(128) __nv_bfloat16 g_h1hi[(size_t)NN_PAD * 128];  // h1 bf16 split (padding stays 0)
__device__ __align__(128) __nv_bfloat16 g_h1lo[(size_t)NN_PAD * 128];
__device__ __align__(128) float g_invdeg[NN_PAD];
__device__ __align__(128) int   g_deg[NN_PAD];
__device__ __align__(128) int   g_start[NN_PAD];
__device__ __align__(128) int   g_cursor[NN_PAD];
__device__ __align__(128) int   g_csr[E_MAX];
__device__ __align__(128) int   g_flags[64];
__device__ __align__(128) __nv_bfloat16 g_Bt1hi[256 * 128];   // W1^T (n,k) bf16 hi/lo
__device__ __align__(128) __nv_bfloat16 g_Bt1lo[256 * 128];
__device__ __align__(128) __nv_bfloat16 g_Bt2hi[128 * 128];
__device__ __align__(128) __nv_bfloat16 g_Bt2lo[128 * 128];

__device__ __forceinline__ uint32_t pack_bf2(__nv_bfloat16 a, __nv_bfloat16 b) {
    __nv_bfloat162 t = __halves2bfloat162(a, b);
    return *reinterpret_cast<uint32_t*>(&t);
}

// ---------------- weight prep (both layers, one launch): W^T + bf16 hi/lo split ----------------
__global__ void k_prepW_all(const float* __restrict__ Ws1, const float* __restrict__ Wn1,
                            const float* __restrict__ Ws2, const float* __restrict__ Wn2,
                            __nv_bfloat16* __restrict__ B1hi, __nv_bfloat16* __restrict__ B1lo,
                            __nv_bfloat16* __restrict__ B2hi, __nv_bfloat16* __restrict__ B2lo) {
    int idx = blockIdx.x * blockDim.x + threadIdx.x;
    if (idx < 256 * 128) {
        int n = idx >> 7, k = idx & 127;
        float v = (n < 128) ? Ws1[k * 128 + n] : Wn1[k * 128 + (n - 128)];
        __nv_bfloat16 h = __float2bfloat16(v);
        B1hi[idx] = h;
        B1lo[idx] = __float2bfloat16(v - __bfloat162float(h));
    } else if (idx < 256 * 128 + 128 * 128) {
        int i2 = idx - 256 * 128;
        int n = i2 >> 7, k = i2 & 127;
        float v = (n < 64) ? Ws2[k * 64 + n] : Wn2[k * 64 + (n - 64)];
        __nv_bfloat16 h = __float2bfloat16(v);
        B2hi[i2] = h;
        B2lo[i2] = __float2bfloat16(v - __bfloat162float(h));
    }
}

// ---------------- CSR build: histogram -> fused scan -> scatter ----------------
__global__ void k_hist(const int* __restrict__ dst, int* __restrict__ deg,
                       int* __restrict__ flags, int E) {
    int i = blockIdx.x * blockDim.x + threadIdx.x;
    if (i < 64) flags[i] = 0;                     // zero scan flags (read only after this kernel)
    if (i < E) atomicAdd(deg + __ldg(dst + i), 1);
}

// single-launch scan: per-block inclusive scan + inter-block prefix propagation (grid <= 64 < #SM)
__global__ __launch_bounds__(1024) void k_scan_fused(
    const int* __restrict__ deg, int* __restrict__ flags,
    int* __restrict__ start, int* __restrict__ cursor,
    float* __restrict__ invdeg, int Nn)
{
    __shared__ int sh[1024];
    __shared__ int s_prefix;
    int i = blockIdx.x * 1024 + threadIdx.x;
    int v = (i < Nn) ? deg[i] : 0;
    sh[threadIdx.x] = v;
    __syncthreads();
#pragma unroll
    for (int o = 1; o < 1024; o <<= 1) {
        int t = (threadIdx.x >= o) ? sh[threadIdx.x - o] : 0;
        __syncthreads();
        sh[threadIdx.x] += t;
        __syncthreads();
    }
    int incl = sh[threadIdx.x];
    if (threadIdx.x == 1023) {
        int prefix = 0;
        if (blockIdx.x > 0) {
            int t;
            while ((t = atomicAdd(flags + blockIdx.x - 1, 0)) == 0) {}
            prefix = t - 1;                       // stored value = inclusive prefix + 1
        }
        atomicExch(flags + blockIdx.x, prefix + incl + 1);
        s_prefix = prefix;
    }
    __syncthreads();
    if (i < Nn) {
        int s = s_prefix + incl - v;
        start[i]  = s;
        cursor[i] = s;
        invdeg[i] = 1.0f / fmaxf((float)v, 1.0f);
    }
}

__global__ void k_scatter(const int* __restrict__ src, const int* __restrict__ dst,
                          int* __restrict__ cursor, int* __restrict__ csr, int E) {
    int i = blockIdx.x * blockDim.x + threadIdx.x;
    if (i < E) {
        int p = atomicAdd(cursor + __ldg(dst + i), 1);
        csr[p] = __ldg(src + i);
    }
}

// ---------------- bf16x3 mma.sync GEMM: [self fp32 | neigh fp16] = A[M,128] @ Bt[N,128]^T ----------------
__device__ __forceinline__ void mma_bf16(float* d, const uint32_t* a, const uint32_t* b) {
    asm volatile(
        "mma.sync.aligned.m16n8k16.row.col.f32.bf16.bf16.f32 "
        "{%0,%1,%2,%3}, {%4,%5,%6,%7}, {%8,%9}, {%0,%1,%2,%3};"
        : "+f"(d[0]), "+f"(d[1]), "+f"(d[2]), "+f"(d[3])
        : "r"(a[0]), "r"(a[1]), "r"(a[2]), "r"(a[3]), "r"(b[0]), "r"(b[1]));
}

#define SMEM_STRIDE 72   // bf16 per row (64 data + 8 pad)

__device__ __forceinline__ uint32_t lds_pair(const __nv_bfloat16* s, int r, int c) {
    return *reinterpret_cast<const uint32_t*>(s + r * SMEM_STRIDE + c);
}

// BM=128, BN=128, BK=64, 256 threads = 8 warps 2(M)x4(N), warp tile 64x32.
// Cols < ncut -> Cself fp32 (stride ncut); cols >= ncut -> Cn fp16 (stride N-ncut).
__global__ __launch_bounds__(256, 2) void gemm_bf16x3(
    const float* __restrict__ A32,
    const __nv_bfloat16* __restrict__ Ahi_g, const __nv_bfloat16* __restrict__ Alo_g,
    const __nv_bfloat16* __restrict__ Bhi_g, const __nv_bfloat16* __restrict__ Blo_g,
    float* __restrict__ Cself, __half* __restrict__ Cn, int M, int N, int ncut)
{
    extern __shared__ __nv_bfloat16 smem[];
    __nv_bfloat16* sAhi = smem;                       // 128 x 72
    __nv_bfloat16* sAlo = sAhi + 128 * SMEM_STRIDE;
    __nv_bfloat16* sBhi = sAlo + 128 * SMEM_STRIDE;
    __nv_bfloat16* sBlo = sBhi + 128 * SMEM_STRIDE;

    const int tid  = threadIdx.x;
    const int warp = tid >> 5;
    const int lane = tid & 31;
    const int g    = lane >> 2;
    const int tig  = lane & 3;
    const int wm   = warp & 1;
    const int wn   = warp >> 1;
    const int bm   = blockIdx.y * 128;
    const int bnb  = blockIdx.x * 128;

    float acc[4][4][4];
#pragma unroll
    for (int mi = 0; mi < 4; mi++)
#pragma unroll
        for (int ni = 0; ni < 4; ni++)
#pragma unroll
            for (int f = 0; f < 4; f++) acc[mi][ni][f] = 0.f;

    for (int kk = 0; kk < 128; kk += 64) {
        if (kk) __syncthreads();

        if (A32 != nullptr) {
#pragma unroll
            for (int i = 0; i < 8; i++) {
                int idx = tid + i * 256;
                int r = idx >> 4, c4 = (idx & 15) * 4;
                float4 v = make_float4(0.f, 0.f, 0.f, 0.f);
                if (bm + r < M)
                    v = *reinterpret_cast<const float4*>(A32 + (size_t)(bm + r) * 128 + kk + c4);
                __nv_bfloat16 hx = __float2bfloat16(v.x), hy = __float2bfloat16(v.y);
                __nv_bfloat16 hz = __float2bfloat16(v.z), hw = __float2bfloat16(v.w);
                __nv_bfloat16 lx = __float2bfloat16(v.x - __bfloat162float(hx));
                __nv_bfloat16 ly = __float2bfloat16(v.y - __bfloat162float(hy));
                __nv_bfloat16 lz = __float2bfloat16(v.z - __bfloat162float(hz));
                __nv_bfloat16 lw = __float2bfloat16(v.w - __bfloat162float(hw));
                int o = r * SMEM_STRIDE + c4;
                *reinterpret_cast<uint2*>(sAhi + o) = make_uint2(pack_bf2(hx, hy), pack_bf2(hz, hw));
                *reinterpret_cast<uint2*>(sAlo + o) = make_uint2(pack_bf2(lx, ly), pack_bf2(lz, lw));
            }
        } else {
#pragma unroll
            for (int i = 0; i < 8; i++) {
                int idx = tid + i * 256;
                int r = idx >> 4, c4 = (idx & 15) * 4;
                int o = r * SMEM_STRIDE + c4;
                *reinterpret_cast<uint2*>(sAhi + o) =
                    *reinterpret_cast<const uint2*>(Ahi_g + (size_t)(bm + r) * 128 + kk + c4);
                *reinterpret_cast<uint2*>(sAlo + o) =
                    *reinterpret_cast<const uint2*>(Alo_g + (size_t)(bm + r) * 128 + kk + c4);
            }
        }

#pragma unroll
        for (int i = 0; i < 8; i++) {
            int idx = tid + i * 256;
            int n = idx >> 4, c4 = (idx & 15) * 4;
            int o = n * SMEM_STRIDE + c4;
            *reinterpret_cast<uint2*>(sBhi + o) =
                *reinterpret_cast<const uint2*>(Bhi_g + (size_t)(bnb + n) * 128 + kk + c4);
            *reinterpret_cast<uint2*>(sBlo + o) =
                *reinterpret_cast<const uint2*>(Blo_g + (size_t)(bnb + n) * 128 + kk + c4);
        }
        __syncthreads();

#pragma unroll
        for (int k16 = 0; k16 < 4; k16++) {
            const int c0 = k16 * 16 + tig * 2;
            uint32_t ah[4][4];
#pragma unroll
            for (int mi = 0; mi < 4; mi++) {
                int r0 = wm * 64 + mi * 16 + g;
                ah[mi][0] = lds_pair(sAhi, r0,     c0);
                ah[mi][1] = lds_pair(sAhi, r0 + 8, c0);
                ah[mi][2] = lds_pair(sAhi, r0,     c0 + 8);
                ah[mi][3] = lds_pair(sAhi, r0 + 8, c0 + 8);
            }
            uint32_t bh[4][2];
#pragma unroll
            for (int ni = 0; ni < 4; ni++) {
                int n0 = wn * 32 + ni * 8 + g;
                bh[ni][0] = lds_pair(sBhi, n0, c0);
                bh[ni][1] = lds_pair(sBhi, n0, c0 + 8);
            }
#pragma unroll
            for (int mi = 0; mi < 4; mi++)
#pragma unroll
                for (int ni = 0; ni < 4; ni++) mma_bf16(acc[mi][ni], ah[mi], bh[ni]);

            uint32_t al[4][4];
#pragma unroll
            for (int mi = 0; mi < 4; mi++) {
                int r0 = wm * 64 + mi * 16 + g;
                al[mi][0] = lds_pair(sAlo, r0,     c0);
                al[mi][1] = lds_pair(sAlo, r0 + 8, c0);
                al[mi][2] = lds_pair(sAlo, r0,     c0 + 8);
                al[mi][3] = lds_pair(sAlo, r0 + 8, c0 + 8);
            }
#pragma unroll
            for (int mi = 0; mi < 4; mi++)
#pragma unroll
                for (int ni = 0; ni < 4; ni++) mma_bf16(acc[mi][ni], al[mi], bh[ni]);

            uint32_t bl[4][2];
#pragma unroll
            for (int ni = 0; ni < 4; ni++) {
                int n0 = wn * 32 + ni * 8 + g;
                bl[ni][0] = lds_pair(sBlo, n0, c0);
                bl[ni][1] = lds_pair(sBlo, n0, c0 + 8);
            }
#pragma unroll
            for (int mi = 0; mi < 4; mi++)
#pragma unroll
                for (int ni = 0; ni < 4; ni++) mma_bf16(acc[mi][ni], ah[mi], bl[ni]);
        }
    }

    // epilogue: self half -> fp32 Cself[*, ncut]; neigh half -> fp16 Cn[*, N-ncut]
    const int nw = N - ncut;
#pragma unroll
    for (int mi = 0; mi < 4; mi++) {
#pragma unroll
        for (int ni = 0; ni < 4; ni++) {
            int row = bm + wm * 64 + mi * 16 + g;
            int col = bnb + wn * 32 + ni * 8 + tig * 2;
            if (col < ncut) {
                *reinterpret_cast<float2*>(Cself + (size_t)row * ncut + col) =
                    make_float2(acc[mi][ni][0], acc[mi][ni][1]);
                *reinterpret_cast<float2*>(Cself + (size_t)(row + 8) * ncut + col) =
                    make_float2(acc[mi][ni][2], acc[mi][ni][3]);
            } else {
                int c = col - ncut;
                *reinterpret_cast<__half2*>(Cn + (size_t)row * nw + c) =
                    __floats2half2_rn(acc[mi][ni][0], acc[mi][ni][1]);
                *reinterpret_cast<__half2*>(Cn + (size_t)(row + 8) * nw + c) =
                    __floats2half2_rn(acc[mi][ni][2], acc[mi][ni][3]);
            }
        }
    }
}

// ---------------- fused CSR aggregation + combine ----------------
__device__ __forceinline__ void acc_half4(float4& acc, uint2 u) {
    float2 f0 = __half22float2(*reinterpret_cast<__half2*>(&u.x));
    float2 f1 = __half22float2(*reinterpret_cast<__half2*>(&u.y));
    acc.x += f0.x; acc.y += f0.y; acc.z += f1.x; acc.w += f1.y;
}

// Layer 1: warp per node; gathers fp16 messages (256B/row); writes h1 as bf16 hi/lo split.
__global__ __launch_bounds__(256) void k_aggcomb1(
    const float* __restrict__ t1s, const __half* __restrict__ t1n,
    const int* __restrict__ csr, const int* __restrict__ start, const int* __restrict__ deg,
    const float* __restrict__ invdeg, const float* __restrict__ b1,
    __nv_bfloat16* __restrict__ h1hi, __nv_bfloat16* __restrict__ h1lo, int Nn)
{
    int warp = (blockIdx.x * blockDim.x + threadIdx.x) >> 5;
    int lane = threadIdx.x & 31;
    if (warp >= Nn) return;
    int s0 = __ldg(start + warp);
    int d  = __ldg(deg + warp);

    float4 acc = make_float4(0.f, 0.f, 0.f, 0.f);
    int i = 0;
    for (; i + 4 <= d; i += 4) {
        int n0 = __ldg(csr + s0 + i);
        int n1 = __ldg(csr + s0 + i + 1);
        int n2 = __ldg(csr + s0 + i + 2);
        int n3 = __ldg(csr + s0 + i + 3);
        uint2 u0 = __ldg(reinterpret_cast<const uint2*>(t1n + (size_t)n0 * 128) + lane);
        uint2 u1 = __ldg(reinterpret_cast<const uint2*>(t1n + (size_t)n1 * 128) + lane);
        uint2 u2 = __ldg(reinterpret_cast<const uint2*>(t1n + (size_t)n2 * 128) + lane);
        uint2 u3 = __ldg(reinterpret_cast<const uint2*>(t1n + (size_t)n3 * 128) + lane);
        acc_half4(acc, u0); acc_half4(acc, u1); acc_half4(acc, u2); acc_half4(acc, u3);
    }
    for (; i < d; i++) {
        int n0 = __ldg(csr + s0 + i);
        uint2 u0 = __ldg(reinterpret_cast<const uint2*>(t1n + (size_t)n0 * 128) + lane);
        acc_half4(acc, u0);
    }

    float inv = __ldg(invdeg + warp);
    float4 sf = *(reinterpret_cast<const float4*>(t1s + (size_t)warp * 128) + lane);
    float4 bb = __ldg(reinterpret_cast<const float4*>(b1) + lane);
    float o[4];
    o[0] = fmaxf(fmaf(acc.x, inv, sf.x + bb.x), 0.f);
    o[1] = fmaxf(fmaf(acc.y, inv, sf.y + bb.y), 0.f);
    o[2] = fmaxf(fmaf(acc.z, inv, sf.z + bb.z), 0.f);
    o[3] = fmaxf(fmaf(acc.w, inv, sf.w + bb.w), 0.f);

    uint32_t hi[2], lo[2];
#pragma unroll
    for (int j = 0; j < 2; j++) {
        __nv_bfloat16 ha = __float2bfloat16(o[2 * j]);
        __nv_bfloat16 hb = __float2bfloat16(o[2 * j + 1]);
        __nv_bfloat16 la = __float2bfloat16(o[2 * j] - __bfloat162float(ha));
        __nv_bfloat16 lb = __float2bfloat16(o[2 * j + 1] - __bfloat162float(hb));
        hi[j] = pack_bf2(ha, hb);
        lo[j] = pack_bf2(la, lb);
    }
    *(reinterpret_cast<uint2*>(h1hi + (size_t)warp * 128) + lane) = make_uint2(hi[0], hi[1]);
    *(reinterpret_cast<uint2*>(h1lo + (size_t)warp * 128) + lane) = make_uint2(lo[0], lo[1]);
}

// Layer 2: half-warp per node; gathers fp16 messages (128B/row). out = t2s + mean*inv + b2
__global__ __launch_bounds__(256) void k_aggcomb2(
    const float* __restrict__ t2s, const __half* __restrict__ t2n,
    const int* __restrict__ csr, const int* __restrict__ start, const int* __restrict__ deg,
    const float* __restrict__ invdeg, const float* __restrict__ b2,
    float* __restrict__ out, int Nn)
{
    int gtid = blockIdx.x * blockDim.x + threadIdx.x;
    int node = gtid >> 4;
    int l    = threadIdx.x & 15;
    if (node >= Nn) return;
    int s0 = __ldg(start + node);
    int d  = __ldg(deg + node);

    float4 acc = make_float4(0.f, 0.f, 0.f, 0.f);
    int i = 0;
    for (; i + 4 <= d; i += 4) {
        int n0 = __ldg(csr + s0 + i);
        int n1 = __ldg(csr + s0 + i + 1);
        int n2 = __ldg(csr + s0 + i + 2);
        int n3 = __ldg(csr + s0 + i + 3);
        uint2 u0 = __ldg(reinterpret_cast<const uint2*>(t2n + (size_t)n0 * 64) + l);
        uint2 u1 = __ldg(reinterpret_cast<const uint2*>(t2n + (size_t)n1 * 64) + l);
        uint2 u2 = __ldg(reinterpret_cast<const uint2*>(t2n + (size_t)n2 * 64) + l);
        uint2 u3 = __ldg(reinterpret_cast<const uint2*>(t2n + (size_t)n3 * 64) + l);
        acc_half4(acc, u0); acc_half4(acc, u1); acc_half4(acc, u2); acc_half4(acc, u3);
    }
    for (; i < d; i++) {
        int n0 = __ldg(csr + s0 + i);
        uint2 u0 = __ldg(reinterpret_cast<const uint2*>(t2n + (size_t)n0 * 64) + l);
        acc_half4(acc, u0);
    }

    float inv = __ldg(invdeg + node);
    float4 sf = *(reinterpret_cast<const float4*>(t2s + (size_t)node * 64) + l);
    float4 bb = __ldg(reinterpret_cast<const float4*>(b2) + l);
    float4 o;
    o.x = fmaf(acc.x, inv, sf.x + bb.x);
    o.y = fmaf(acc.y, inv, sf.y + bb.y);
    o.z = fmaf(acc.z, inv, sf.z + bb.z);
    o.w = fmaf(acc.w, inv, sf.w + bb.w);
    *(reinterpret_cast<float4*>(out + (size_t)node * 64) + l) = o;
}

// ---------------- launch ----------------
extern "C" void kernel_launch(void* const* d_in, const int* in_sizes, int n_in,
                              void* d_out, int out_size)
{
    const float* x   = (const float*)d_in[0];
    const float* Ws1 = (const float*)d_in[1];
    const float* Wn1 = (const float*)d_in[2];
    const float* b1  = (const float*)d_in[3];
    const float* Ws2 = (const float*)d_in[4];
    const float* Wn2 = (const float*)d_in[5];
    const float* b2  = (const float*)d_in[6];
    const int*   src = (const int*)d_in[7];
    const int*   dst = (const int*)d_in[8];
    float* out = (float*)d_out;

    int Nn = in_sizes[0] / NF;
    int E  = in_sizes[7];

    float *t1s, *t2s, *invdeg;
    __half *t1n, *t2n;
    __nv_bfloat16 *h1hi, *h1lo, *Bt1hi, *Bt1lo, *Bt2hi, *Bt2lo;
    int *deg, *start, *cursor, *csr, *flags;
    cudaGetSymbolAddress((void**)&t1s,    g_t1s);
    cudaGetSymbolAddress((void**)&t1n,    g_t1n);
    cudaGetSymbolAddress((void**)&t2s,    g_t2s);
    cudaGetSymbolAddress((void**)&t2n,    g_t2n);
    cudaGetSymbolAddress((void**)&h1hi,   g_h1hi);
    cudaGetSymbolAddress((void**)&h1lo,   g_h1lo);
    cudaGetSymbolAddress((void**)&invdeg, g_invdeg);
    cudaGetSymbolAddress((void**)&deg,    g_deg);
    cudaGetSymbolAddress((void**)&start,  g_start);
    cudaGetSymbolAddress((void**)&cursor, g_cursor);
    cudaGetSymbolAddress((void**)&csr,    g_csr);
    cudaGetSymbolAddress((void**)&flags,  g_flags);
    cudaGetSymbolAddress((void**)&Bt1hi,  g_Bt1hi);
    cudaGetSymbolAddress((void**)&Bt1lo,  g_Bt1lo);
    cudaGetSymbolAddress((void**)&Bt2hi,  g_Bt2hi);
    cudaGetSymbolAddress((void**)&Bt2lo,  g_Bt2lo);

    const int SMEM = 4 * 128 * SMEM_STRIDE * (int)sizeof(__nv_bfloat16);   // 73728
    cudaFuncSetAttribute(gemm_bf16x3, cudaFuncAttributeMaxDynamicSharedMemorySize, SMEM);

    int nblk = (Nn + 1023) / 1024;
    int nmt  = (Nn + 127) / 128;

    // CSR build (4 nodes)
    cudaMemsetAsync(deg, 0, (size_t)Nn * sizeof(int));
    k_hist<<<(E + 255) / 256, 256>>>(dst, deg, flags, E);
    k_scan_fused<<<nblk, 1024>>>(deg, flags, start, cursor, invdeg, Nn);
    k_scatter<<<(E + 255) / 256, 256>>>(src, dst, cursor, csr, E);

    // weight prep (1 node)
    k_prepW_all<<<(256 * 128 + 128 * 128 + 255) / 256, 256>>>(Ws1, Wn1, Ws2, Wn2,
                                                              Bt1hi, Bt1lo, Bt2hi, Bt2lo);

    // Layer 1
    gemm_bf16x3<<<dim3(2, nmt), 256, SMEM>>>(x, nullptr, nullptr, Bt1hi, Bt1lo,
                                             t1s, t1n, Nn, 256, 128);
    k_aggcomb1<<<(Nn * 32 + 255) / 256, 256>>>(t1s, t1n, csr, start, deg, invdeg, b1,
                                               h1hi, h1lo, Nn);

    // Layer 2
    gemm_bf16x3<<<dim3(1, nmt), 256, SMEM>>>(nullptr, h1hi, h1lo, Bt2hi, Bt2lo,
                                             t2s, t2n, Nn, 128, 64);
    k_aggcomb2<<<(Nn * 16 + 255) / 256, 256>>>(t2s, t2n, csr, start, deg, invdeg, b2, out, Nn);
}

// round 15
// speedup vs baseline: 2.5951x; 1.1896x over previous
#include <cuda_runtime.h>
#include <cuda_bf16.h>
#include <cuda_fp16.h>
#include <cstdint>

// Problem constants (fixed by the reference)
#define NN_PAD 50176          // 392 * 128, padded node count
#define E_MAX  840000
#define NF 128

// ---------------- static scratch (no allocations allowed) ----------------
__device__ __align__(128) float  g_t1s[(size_t)NN_PAD * 128];  // GEMM1 self half (fp32)
__device__ __align__(128) __half g_t1n[(size_t)NN_PAD * 128];  // GEMM1 neigh half (fp16 messages)
__device__ __align__(128) float  g_t2s[(size_t)NN_PAD * 64];   // GEMM2 self half (fp32)
__device__ __align__(128) __half g_t2n[(size_t)NN_PAD * 64];   // GEMM2 neigh half (fp16 messages)
__device__ __align__(128) __nv_bfloat16 g_h1hi[(size_t)NN_PAD * 128];  // h1 bf16 split (padding stays 0)
__device__ __align__(128) __nv_bfloat16 g_h1lo[(size_t)NN_PAD * 128];
__device__ __align__(128) float g_invdeg[NN_PAD];
__device__ __align__(128) int   g_deg[NN_PAD];     // zero-initialized; scan re-zeroes every call
__device__ __align__(128) int   g_start[NN_PAD];
__device__ __align__(128) int   g_cursor[NN_PAD];  // post-scatter: cursor[i] == row end
__device__ __align__(128) int   g_csr[E_MAX];
__device__ __align__(128) int   g_flags[64];       // zero-initialized; scatter re-zeroes every call
__device__ __align__(128) __nv_bfloat16 g_Bt1hi[256 * 128];   // W1^T (n,k) bf16 hi/lo
__device__ __align__(128) __nv_bfloat16 g_Bt1lo[256 * 128];
__device__ __align__(128) __nv_bfloat16 g_Bt2hi[128 * 128];
__device__ __align__(128) __nv_bfloat16 g_Bt2lo[128 * 128];

__device__ __forceinline__ uint32_t pack_bf2(__nv_bfloat16 a, __nv_bfloat16 b) {
    __nv_bfloat162 t = __halves2bfloat162(a, b);
    return *reinterpret_cast<uint32_t*>(&t);
}

// ---------------- weight prep (both layers, one launch): W^T + bf16 hi/lo split ----------------
__global__ void k_prepW_all(const float* __restrict__ Ws1, const float* __restrict__ Wn1,
                            const float* __restrict__ Ws2, const float* __restrict__ Wn2,
                            __nv_bfloat16* __restrict__ B1hi, __nv_bfloat16* __restrict__ B1lo,
                            __nv_bfloat16* __restrict__ B2hi, __nv_bfloat16* __restrict__ B2lo) {
    int idx = blockIdx.x * blockDim.x + threadIdx.x;
    if (idx < 256 * 128) {
        int n = idx >> 7, k = idx & 127;
        float v = (n < 128) ? Ws1[k * 128 + n] : Wn1[k * 128 + (n - 128)];
        __nv_bfloat16 h = __float2bfloat16(v);
        B1hi[idx] = h;
        B1lo[idx] = __float2bfloat16(v - __bfloat162float(h));
    } else if (idx < 256 * 128 + 128 * 128) {
        int i2 = idx - 256 * 128;
        int n = i2 >> 7, k = i2 & 127;
        float v = (n < 64) ? Ws2[k * 64 + n] : Wn2[k * 64 + (n - 64)];
        __nv_bfloat16 h = __float2bfloat16(v);
        B2hi[i2] = h;
        B2lo[i2] = __float2bfloat16(v - __bfloat162float(h));
    }
}

// ---------------- CSR build: histogram -> fused scan -> scatter (side stream) ----------------
__global__ void k_hist(const int* __restrict__ dst, int* __restrict__ deg, int E) {
    int i = blockIdx.x * blockDim.x + threadIdx.x;
    if (i < E) atomicAdd(deg + __ldg(dst + i), 1);
}

// single-launch scan: per-block inclusive scan + inter-block prefix propagation (grid <= 64 < #SM)
// Also zeroes deg[] behind itself (restores state for the next graph replay).
__global__ __launch_bounds__(1024) void k_scan_fused(
    int* __restrict__ deg, int* __restrict__ flags,
    int* __restrict__ start, int* __restrict__ cursor,
    float* __restrict__ invdeg, int Nn)
{
    __shared__ int sh[1024];
    __shared__ int s_prefix;
    int i = blockIdx.x * 1024 + threadIdx.x;
    int v = (i < Nn) ? deg[i] : 0;
    if (i < Nn) deg[i] = 0;                       // restore for next replay
    sh[threadIdx.x] = v;
    __syncthreads();
#pragma unroll
    for (int o = 1; o < 1024; o <<= 1) {
        int t = (threadIdx.x >= o) ? sh[threadIdx.x - o] : 0;
        __syncthreads();
        sh[threadIdx.x] += t;
        __syncthreads();
    }
    int incl = sh[threadIdx.x];
    if (threadIdx.x == 1023) {
        int prefix = 0;
        if (blockIdx.x > 0) {
            int t;
            while ((t = atomicAdd(flags + blockIdx.x - 1, 0)) == 0) {}
            prefix = t - 1;                       // stored value = inclusive prefix + 1
        }
        atomicExch(flags + blockIdx.x, prefix + incl + 1);
        s_prefix = prefix;
    }
    __syncthreads();
    if (i < Nn) {
        int s = s_prefix + incl - v;
        start[i]  = s;
        cursor[i] = s;
        invdeg[i] = 1.0f / fmaxf((float)v, 1.0f);
    }
}

// scatter src ids into CSR; also zeroes scan flags (all scan blocks finished by now).
__global__ void k_scatter(const int* __restrict__ src, const int* __restrict__ dst,
                          int* __restrict__ cursor, int* __restrict__ csr,
                          int* __restrict__ flags, int E) {
    int i = blockIdx.x * blockDim.x + threadIdx.x;
    if (i < 64) flags[i] = 0;                     // restore for next replay
    if (i < E) {
        int p = atomicAdd(cursor + __ldg(dst + i), 1);
        csr[p] = __ldg(src + i);
    }
}

// ---------------- bf16x3 mma.sync GEMM: [self fp32 | neigh fp16] = A[M,128] @ Bt[N,128]^T ----------------
__device__ __forceinline__ void mma_bf16(float* d, const uint32_t* a, const uint32_t* b) {
    asm volatile(
        "mma.sync.aligned.m16n8k16.row.col.f32.bf16.bf16.f32 "
        "{%0,%1,%2,%3}, {%4,%5,%6,%7}, {%8,%9}, {%0,%1,%2,%3};"
        : "+f"(d[0]), "+f"(d[1]), "+f"(d[2]), "+f"(d[3])
        : "r"(a[0]), "r"(a[1]), "r"(a[2]), "r"(a[3]), "r"(b[0]), "r"(b[1]));
}

#define SMEM_STRIDE 72   // bf16 per row (64 data + 8 pad)

__device__ __forceinline__ uint32_t lds_pair(const __nv_bfloat16* s, int r, int c) {
    return *reinterpret_cast<const uint32_t*>(s + r * SMEM_STRIDE + c);
}

// BM=128, BN=128, BK=64, 256 threads = 8 warps 2(M)x4(N), warp tile 64x32.
// Cols < ncut -> Cself fp32 (stride ncut); cols >= ncut -> Cn fp16 (stride N-ncut).
__global__ __launch_bounds__(256, 2) void gemm_bf16x3(
    const float* __restrict__ A32,
    const __nv_bfloat16* __restrict__ Ahi_g, const __nv_bfloat16* __restrict__ Alo_g,
    const __nv_bfloat16* __restrict__ Bhi_g, const __nv_bfloat16* __restrict__ Blo_g,
    float* __restrict__ Cself, __half* __restrict__ Cn, int M, int N, int ncut)
{
    extern __shared__ __nv_bfloat16 smem[];
    __nv_bfloat16* sAhi = smem;                       // 128 x 72
    __nv_bfloat16* sAlo = sAhi + 128 * SMEM_STRIDE;
    __nv_bfloat16* sBhi = sAlo + 128 * SMEM_STRIDE;
    __nv_bfloat16* sBlo = sBhi + 128 * SMEM_STRIDE;

    const int tid  = threadIdx.x;
    const int warp = tid >> 5;
    const int lane = tid & 31;
    const int g    = lane >> 2;
    const int tig  = lane & 3;
    const int wm   = warp & 1;
    const int wn   = warp >> 1;
    const int bm   = blockIdx.y * 128;
    const int bnb  = blockIdx.x * 128;

    float acc[4][4][4];
#pragma unroll
    for (int mi = 0; mi < 4; mi++)
#pragma unroll
        for (int ni = 0; ni < 4; ni++)
#pragma unroll
            for (int f = 0; f < 4; f++) acc[mi][ni][f] = 0.f;

    for (int kk = 0; kk < 128; kk += 64) {
        if (kk) __syncthreads();

        if (A32 != nullptr) {
#pragma unroll
            for (int i = 0; i < 8; i++) {
                int idx = tid + i * 256;
                int r = idx >> 4, c4 = (idx & 15) * 4;
                float4 v = make_float4(0.f, 0.f, 0.f, 0.f);
                if (bm + r < M)
                    v = *reinterpret_cast<const float4*>(A32 + (size_t)(bm + r) * 128 + kk + c4);
                __nv_bfloat16 hx = __float2bfloat16(v.x), hy = __float2bfloat16(v.y);
                __nv_bfloat16 hz = __float2bfloat16(v.z), hw = __float2bfloat16(v.w);
                __nv_bfloat16 lx = __float2bfloat16(v.x - __bfloat162float(hx));
                __nv_bfloat16 ly = __float2bfloat16(v.y - __bfloat162float(hy));
                __nv_bfloat16 lz = __float2bfloat16(v.z - __bfloat162float(hz));
                __nv_bfloat16 lw = __float2bfloat16(v.w - __bfloat162float(hw));
                int o = r * SMEM_STRIDE + c4;
                *reinterpret_cast<uint2*>(sAhi + o) = make_uint2(pack_bf2(hx, hy), pack_bf2(hz, hw));
                *reinterpret_cast<uint2*>(sAlo + o) = make_uint2(pack_bf2(lx, ly), pack_bf2(lz, lw));
            }
        } else {
#pragma unroll
            for (int i = 0; i < 8; i++) {
                int idx = tid + i * 256;
                int r = idx >> 4, c4 = (idx & 15) * 4;
                int o = r * SMEM_STRIDE + c4;
                *reinterpret_cast<uint2*>(sAhi + o) =
                    *reinterpret_cast<const uint2*>(Ahi_g + (size_t)(bm + r) * 128 + kk + c4);
                *reinterpret_cast<uint2*>(sAlo + o) =
                    *reinterpret_cast<const uint2*>(Alo_g + (size_t)(bm + r) * 128 + kk + c4);
            }
        }

#pragma unroll
        for (int i = 0; i < 8; i++) {
            int idx = tid + i * 256;
            int n = idx >> 4, c4 = (idx & 15) * 4;
            int o = n * SMEM_STRIDE + c4;
            *reinterpret_cast<uint2*>(sBhi + o) =
                *reinterpret_cast<const uint2*>(Bhi_g + (size_t)(bnb + n) * 128 + kk + c4);
            *reinterpret_cast<uint2*>(sBlo + o) =
                *reinterpret_cast<const uint2*>(Blo_g + (size_t)(bnb + n) * 128 + kk + c4);
        }
        __syncthreads();

#pragma unroll
        for (int k16 = 0; k16 < 4; k16++) {
            const int c0 = k16 * 16 + tig * 2;
            uint32_t ah[4][4];
#pragma unroll
            for (int mi = 0; mi < 4; mi++) {
                int r0 = wm * 64 + mi * 16 + g;
                ah[mi][0] = lds_pair(sAhi, r0,     c0);
                ah[mi][1] = lds_pair(sAhi, r0 + 8, c0);
                ah[mi][2] = lds_pair(sAhi, r0,     c0 + 8);
                ah[mi][3] = lds_pair(sAhi, r0 + 8, c0 + 8);
            }
            uint32_t bh[4][2];
#pragma unroll
            for (int ni = 0; ni < 4; ni++) {
                int n0 = wn * 32 + ni * 8 + g;
                bh[ni][0] = lds_pair(sBhi, n0, c0);
                bh[ni][1] = lds_pair(sBhi, n0, c0 + 8);
            }
#pragma unroll
            for (int mi = 0; mi < 4; mi++)
#pragma unroll
                for (int ni = 0; ni < 4; ni++) mma_bf16(acc[mi][ni], ah[mi], bh[ni]);

            uint32_t al[4][4];
#pragma unroll
            for (int mi = 0; mi < 4; mi++) {
                int r0 = wm * 64 + mi * 16 + g;
                al[mi][0] = lds_pair(sAlo, r0,     c0);
                al[mi][1] = lds_pair(sAlo, r0 + 8, c0);
                al[mi][2] = lds_pair(sAlo, r0,     c0 + 8);
                al[mi][3] = lds_pair(sAlo, r0 + 8, c0 + 8);
            }
#pragma unroll
            for (int mi = 0; mi < 4; mi++)
#pragma unroll
                for (int ni = 0; ni < 4; ni++) mma_bf16(acc[mi][ni], al[mi], bh[ni]);

            uint32_t bl[4][2];
#pragma unroll
            for (int ni = 0; ni < 4; ni++) {
                int n0 = wn * 32 + ni * 8 + g;
                bl[ni][0] = lds_pair(sBlo, n0, c0);
                bl[ni][1] = lds_pair(sBlo, n0, c0 + 8);
            }
#pragma unroll
            for (int mi = 0; mi < 4; mi++)
#pragma unroll
                for (int ni = 0; ni < 4; ni++) mma_bf16(acc[mi][ni], ah[mi], bl[ni]);
        }
    }

    // epilogue: self half -> fp32 Cself[*, ncut]; neigh half -> fp16 Cn[*, N-ncut]
    const int nw = N - ncut;
#pragma unroll
    for (int mi = 0; mi < 4; mi++) {
#pragma unroll
        for (int ni = 0; ni < 4; ni++) {
            int row = bm + wm * 64 + mi * 16 + g;
            int col = bnb + wn * 32 + ni * 8 + tig * 2;
            if (col < ncut) {
                *reinterpret_cast<float2*>(Cself + (size_t)row * ncut + col) =
                    make_float2(acc[mi][ni][0], acc[mi][ni][1]);
                *reinterpret_cast<float2*>(Cself + (size_t)(row + 8) * ncut + col) =
                    make_float2(acc[mi][ni][2], acc[mi][ni][3]);
            } else {
                int c = col - ncut;
                *reinterpret_cast<__half2*>(Cn + (size_t)row * nw + c) =
                    __floats2half2_rn(acc[mi][ni][0], acc[mi][ni][1]);
                *reinterpret_cast<__half2*>(Cn + (size_t)(row + 8) * nw + c) =
                    __floats2half2_rn(acc[mi][ni][2], acc[mi][ni][3]);
            }
        }
    }
}

// ---------------- fused CSR aggregation + combine ----------------
__device__ __forceinline__ void acc_half4(float4& acc, uint2 u) {
    float2 f0 = __half22float2(*reinterpret_cast<__half2*>(&u.x));
    float2 f1 = __half22float2(*reinterpret_cast<__half2*>(&u.y));
    acc.x += f0.x; acc.y += f0.y; acc.z += f1.x; acc.w += f1.y;
}

// Layer 1: warp per node; gathers fp16 messages; writes h1 as bf16 hi/lo split.
// degree = endp[i] - start[i]  (endp = post-scatter cursor)
__global__ __launch_bounds__(256) void k_aggcomb1(
    const float* __restrict__ t1s, const __half* __restrict__ t1n,
    const int* __restrict__ csr, const int* __restrict__ start, const int* __restrict__ endp,
    const float* __restrict__ invdeg, const float* __restrict__ b1,
    __nv_bfloat16* __restrict__ h1hi, __nv_bfloat16* __restrict__ h1lo, int Nn)
{
    int warp = (blockIdx.x * blockDim.x + threadIdx.x) >> 5;
    int lane = threadIdx.x & 31;
    if (warp >= Nn) return;
    int s0 = __ldg(start + warp);
    int d  = __ldg(endp + warp) - s0;

    float4 acc = make_float4(0.f, 0.f, 0.f, 0.f);
    int i = 0;
    for (; i + 4 <= d; i += 4) {
        int n0 = __ldg(csr + s0 + i);
        int n1 = __ldg(csr + s0 + i + 1);
        int n2 = __ldg(csr + s0 + i + 2);
        int n3 = __ldg(csr + s0 + i + 3);
        uint2 u0 = __ldg(reinterpret_cast<const uint2*>(t1n + (size_t)n0 * 128) + lane);
        uint2 u1 = __ldg(reinterpret_cast<const uint2*>(t1n + (size_t)n1 * 128) + lane);
        uint2 u2 = __ldg(reinterpret_cast<const uint2*>(t1n + (size_t)n2 * 128) + lane);
        uint2 u3 = __ldg(reinterpret_cast<const uint2*>(t1n + (size_t)n3 * 128) + lane);
        acc_half4(acc, u0); acc_half4(acc, u1); acc_half4(acc, u2); acc_half4(acc, u3);
    }
    for (; i < d; i++) {
        int n0 = __ldg(csr + s0 + i);
        uint2 u0 = __ldg(reinterpret_cast<const uint2*>(t1n + (size_t)n0 * 128) + lane);
        acc_half4(acc, u0);
    }

    float inv = __ldg(invdeg + warp);
    float4 sf = *(reinterpret_cast<const float4*>(t1s + (size_t)warp * 128) + lane);
    float4 bb = __ldg(reinterpret_cast<const float4*>(b1) + lane);
    float o[4];
    o[0] = fmaxf(fmaf(acc.x, inv, sf.x + bb.x), 0.f);
    o[1] = fmaxf(fmaf(acc.y, inv, sf.y + bb.y), 0.f);
    o[2] = fmaxf(fmaf(acc.z, inv, sf.z + bb.z), 0.f);
    o[3] = fmaxf(fmaf(acc.w, inv, sf.w + bb.w), 0.f);

    uint32_t hi[2], lo[2];
#pragma unroll
    for (int j = 0; j < 2; j++) {
        __nv_bfloat16 ha = __float2bfloat16(o[2 * j]);
        __nv_bfloat16 hb = __float2bfloat16(o[2 * j + 1]);
        __nv_bfloat16 la = __float2bfloat16(o[2 * j] - __bfloat162float(ha));
        __nv_bfloat16 lb = __float2bfloat16(o[2 * j + 1] - __bfloat162float(hb));
        hi[j] = pack_bf2(ha, hb);
        lo[j] = pack_bf2(la, lb);
    }
    *(reinterpret_cast<uint2*>(h1hi + (size_t)warp * 128) + lane) = make_uint2(hi[0], hi[1]);
    *(reinterpret_cast<uint2*>(h1lo + (size_t)warp * 128) + lane) = make_uint2(lo[0], lo[1]);
}

// Layer 2: half-warp per node; gathers fp16 messages. out = t2s + mean + b2
__global__ __launch_bounds__(256) void k_aggcomb2(
    const float* __restrict__ t2s, const __half* __restrict__ t2n,
    const int* __restrict__ csr, const int* __restrict__ start, const int* __restrict__ endp,
    const float* __restrict__ invdeg, const float* __restrict__ b2,
    float* __restrict__ out, int Nn)
{
    int gtid = blockIdx.x * blockDim.x + threadIdx.x;
    int node = gtid >> 4;
    int l    = threadIdx.x & 15;
    if (node >= Nn) return;
    int s0 = __ldg(start + node);
    int d  = __ldg(endp + node) - s0;

    float4 acc = make_float4(0.f, 0.f, 0.f, 0.f);
    int i = 0;
    for (; i + 4 <= d; i += 4) {
        int n0 = __ldg(csr + s0 + i);
        int n1 = __ldg(csr + s0 + i + 1);
        int n2 = __ldg(csr + s0 + i + 2);
        int n3 = __ldg(csr + s0 + i + 3);
        uint2 u0 = __ldg(reinterpret_cast<const uint2*>(t2n + (size_t)n0 * 64) + l);
        uint2 u1 = __ldg(reinterpret_cast<const uint2*>(t2n + (size_t)n1 * 64) + l);
        uint2 u2 = __ldg(reinterpret_cast<const uint2*>(t2n + (size_t)n2 * 64) + l);
        uint2 u3 = __ldg(reinterpret_cast<const uint2*>(t2n + (size_t)n3 * 64) + l);
        acc_half4(acc, u0); acc_half4(acc, u1); acc_half4(acc, u2); acc_half4(acc, u3);
    }
    for (; i < d; i++) {
        int n0 = __ldg(csr + s0 + i);
        uint2 u0 = __ldg(reinterpret_cast<const uint2*>(t2n + (size_t)n0 * 64) + l);
        acc_half4(acc, u0);
    }

    float inv = __ldg(invdeg + node);
    float4 sf = *(reinterpret_cast<const float4*>(t2s + (size_t)node * 64) + l);
    float4 bb = __ldg(reinterpret_cast<const float4*>(b2) + l);
    float4 o;
    o.x = fmaf(acc.x, inv, sf.x + bb.x);
    o.y = fmaf(acc.y, inv, sf.y + bb.y);
    o.z = fmaf(acc.z, inv, sf.z + bb.z);
    o.w = fmaf(acc.w, inv, sf.w + bb.w);
    *(reinterpret_cast<float4*>(out + (size_t)node * 64) + l) = o;
}

// ---------------- launch ----------------
extern "C" void kernel_launch(void* const* d_in, const int* in_sizes, int n_in,
                              void* d_out, int out_size)
{
    const float* x   = (const float*)d_in[0];
    const float* Ws1 = (const float*)d_in[1];
    const float* Wn1 = (const float*)d_in[2];
    const float* b1  = (const float*)d_in[3];
    const float* Ws2 = (const float*)d_in[4];
    const float* Wn2 = (const float*)d_in[5];
    const float* b2  = (const float*)d_in[6];
    const int*   src = (const int*)d_in[7];
    const int*   dst = (const int*)d_in[8];
    float* out = (float*)d_out;

    int Nn = in_sizes[0] / NF;
    int E  = in_sizes[7];

    float *t1s, *t2s, *invdeg;
    __half *t1n, *t2n;
    __nv_bfloat16 *h1hi, *h1lo, *Bt1hi, *Bt1lo, *Bt2hi, *Bt2lo;
    int *deg, *start, *cursor, *csr, *flags;
    cudaGetSymbolAddress((void**)&t1s,    g_t1s);
    cudaGetSymbolAddress((void**)&t1n,    g_t1n);
    cudaGetSymbolAddress((void**)&t2s,    g_t2s);
    cudaGetSymbolAddress((void**)&t2n,    g_t2n);
    cudaGetSymbolAddress((void**)&h1hi,   g_h1hi);
    cudaGetSymbolAddress((void**)&h1lo,   g_h1lo);
    cudaGetSymbolAddress((void**)&invdeg, g_invdeg);
    cudaGetSymbolAddress((void**)&deg,    g_deg);
    cudaGetSymbolAddress((void**)&start,  g_start);
    cudaGetSymbolAddress((void**)&cursor, g_cursor);
    cudaGetSymbolAddress((void**)&csr,    g_csr);
    cudaGetSymbolAddress((void**)&flags,  g_flags);
    cudaGetSymbolAddress((void**)&Bt1hi,  g_Bt1hi);
    cudaGetSymbolAddress((void**)&Bt1lo,  g_Bt1lo);
    cudaGetSymbolAddress((void**)&Bt2hi,  g_Bt2hi);
    cudaGetSymbolAddress((void**)&Bt2lo,  g_Bt2lo);

    const int SMEM = 4 * 128 * SMEM_STRIDE * (int)sizeof(__nv_bfloat16);   // 73728
    static bool s_init = false;
    static cudaStream_t s1;
    static cudaEvent_t ev_fork, ev_join;
    if (!s_init) {
        cudaFuncSetAttribute(gemm_bf16x3, cudaFuncAttributeMaxDynamicSharedMemorySize, SMEM);
        cudaStreamCreateWithFlags(&s1, cudaStreamNonBlocking);
        cudaEventCreateWithFlags(&ev_fork, cudaEventDisableTiming);
        cudaEventCreateWithFlags(&ev_join, cudaEventDisableTiming);
        s_init = true;
    }

    int nblk = (Nn + 1023) / 1024;
    int nmt  = (Nn + 127) / 128;

    // ---- fork: CSR build on side stream, overlapped with weight prep + GEMM1 ----
    cudaEventRecord(ev_fork, 0);
    cudaStreamWaitEvent(s1, ev_fork, 0);

    k_hist<<<(E + 255) / 256, 256, 0, s1>>>(dst, deg, E);
    k_scan_fused<<<nblk, 1024, 0, s1>>>(deg, flags, start, cursor, invdeg, Nn);
    k_scatter<<<(E + 255) / 256, 256, 0, s1>>>(src, dst, cursor, csr, flags, E);
    cudaEventRecord(ev_join, s1);

    // main stream: weight prep + GEMM1 (independent of CSR)
    k_prepW_all<<<(256 * 128 + 128 * 128 + 255) / 256, 256>>>(Ws1, Wn1, Ws2, Wn2,
                                                              Bt1hi, Bt1lo, Bt2hi, Bt2lo);
    gemm_bf16x3<<<dim3(2, nmt), 256, SMEM>>>(x, nullptr, nullptr, Bt1hi, Bt1lo,
                                             t1s, t1n, Nn, 256, 128);

    // ---- join: aggregation needs both GEMM1 and the CSR ----
    cudaStreamWaitEvent(0, ev_join, 0);

    k_aggcomb1<<<(Nn * 32 + 255) / 256, 256>>>(t1s, t1n, csr, start, cursor, invdeg, b1,
                                               h1hi, h1lo, Nn);

    // Layer 2
    gemm_bf16x3<<<dim3(1, nmt), 256, SMEM>>>(nullptr, h1hi, h1lo, Bt2hi, Bt2lo,
                                             t2s, t2n, Nn, 128, 64);
    k_aggcomb2<<<(Nn * 16 + 255) / 256, 256>>>(t2s, t2n, csr, start, cursor, invdeg, b2, out, Nn);
}